// round 12
// baseline (speedup 1.0000x reference)
#include <cuda_runtime.h>
#include <math.h>

static const int MAXN = 50000;
static const int MAXE = 800000 + MAXN;

// ---------------- scratch ----------------
__device__ float g_h1[MAXN * 256];
__device__ float g_o1[MAXN * 256];
__device__ float g_as1[MAXN * 8];
__device__ float g_ad1[MAXN * 8];
__device__ float g_h2[MAXN * 32];
__device__ float g_z[MAXN * 32];
__device__ float g_as2[MAXN];
__device__ float g_ad2[MAXN];
__device__ int   g_cnt[MAXN];
__device__ int   g_row[MAXN + 1];
__device__ int   g_cur[MAXN];
__device__ int   g_bsum[256];
__device__ int   g_boff[256];
__device__ int   g_esrc[MAXE];

__device__ __forceinline__ float lrelu(float v) { return v > 0.f ? v : 0.2f * v; }

// ---------------- GEMM 128x64 SIMT + optional fused alpha epilogue ----------
// C[M,N] = A[M,K] @ B[K,N] (+bias), optional relu(A).
// If als != nullptr: per-row, per-head (32-col) dots with aS/aD ([H,32]) are
// reduced across each tx-octet and written to als/ald ([M,H]). Requires N%32==0
// per covered head; heads per block = 64/32 = 2 (head index = n0/32 + tx/8).
__global__ void gemm_k(const float* __restrict__ A, const float* __restrict__ B,
                       const float* __restrict__ bias, float* __restrict__ C,
                       int M, int N, int K, int reluA,
                       const float* __restrict__ aS, const float* __restrict__ aD,
                       float* __restrict__ als, float* __restrict__ ald, int H) {
    __shared__ float As[16][132];
    __shared__ float Bs[16][64];
    int tid = threadIdx.x;
    int ty = tid >> 4;
    int tx = tid & 15;
    int m0 = blockIdx.y * 128;
    int n0 = blockIdx.x * 64;
    float acc[8][4] = {};

    for (int k0 = 0; k0 < K; k0 += 16) {
        #pragma unroll
        for (int i = 0; i < 2; i++) {
            int L = tid + 256 * i;
            int row = L >> 2, q = (L & 3) << 2;
            float4 v = make_float4(0.f, 0.f, 0.f, 0.f);
            if (m0 + row < M) {
                v = *(const float4*)(A + (size_t)(m0 + row) * K + k0 + q);
                if (reluA) {
                    v.x = fmaxf(v.x, 0.f); v.y = fmaxf(v.y, 0.f);
                    v.z = fmaxf(v.z, 0.f); v.w = fmaxf(v.w, 0.f);
                }
            }
            As[q + 0][row] = v.x; As[q + 1][row] = v.y;
            As[q + 2][row] = v.z; As[q + 3][row] = v.w;
        }
        {
            int kl = tid >> 4, g = (tid & 15) << 2;
            float4 v = make_float4(0.f, 0.f, 0.f, 0.f);
            if (n0 + g < N)
                v = *(const float4*)(B + (size_t)(k0 + kl) * N + n0 + g);
            *(float4*)&Bs[kl][g] = v;
        }
        __syncthreads();
        #pragma unroll
        for (int kk = 0; kk < 16; kk++) {
            float a[8], b[4];
            *(float4*)&a[0] = *(const float4*)&As[kk][ty * 8];
            *(float4*)&a[4] = *(const float4*)&As[kk][ty * 8 + 4];
            *(float4*)&b[0] = *(const float4*)&Bs[kk][tx * 4];
            #pragma unroll
            for (int i = 0; i < 8; i++)
                #pragma unroll
                for (int j = 0; j < 4; j++)
                    acc[i][j] += a[i] * b[j];
        }
        __syncthreads();
    }
    int colb = n0 + tx * 4;
    if (colb < N) {
        float4 bv = make_float4(0.f, 0.f, 0.f, 0.f);
        if (bias) bv = *(const float4*)(bias + colb);
        #pragma unroll
        for (int i = 0; i < 8; i++) {
            int row = m0 + ty * 8 + i;
            if (row >= M) break;
            float4 v = make_float4(acc[i][0] + bv.x, acc[i][1] + bv.y,
                                   acc[i][2] + bv.z, acc[i][3] + bv.w);
            *(float4*)(C + (size_t)row * N + colb) = v;
        }
    }
    // fused alpha epilogue: head = n0/32 + tx/8, octet shfl reduce
    if (als) {
        int hl = tx >> 3;                       // 0 or 1 within block
        int head = (n0 >> 5) + hl;
        float4 cs = make_float4(0.f, 0.f, 0.f, 0.f), cd = cs;
        if (head < H) {
            cs = ((const float4*)aS)[head * 8 + (tx & 7)];
            cd = ((const float4*)aD)[head * 8 + (tx & 7)];
        }
        #pragma unroll
        for (int i = 0; i < 8; i++) {
            float ps = acc[i][0] * cs.x + acc[i][1] * cs.y + acc[i][2] * cs.z + acc[i][3] * cs.w;
            float pd = acc[i][0] * cd.x + acc[i][1] * cd.y + acc[i][2] * cd.z + acc[i][3] * cd.w;
            #pragma unroll
            for (int off = 4; off; off >>= 1) {   // reduce within tx-octet
                ps += __shfl_xor_sync(0xffffffffu, ps, off);
                pd += __shfl_xor_sync(0xffffffffu, pd, off);
            }
            int row = m0 + ty * 8 + i;
            if ((tx & 7) == 0 && head < H && row < M) {
                als[(size_t)row * H + head] = ps;
                ald[(size_t)row * H + head] = pd;
            }
        }
    }
}

// ---------------- CSR build ----------------
__global__ void init_cnt_k(int* cnt, int N) {
    int i = blockIdx.x * blockDim.x + threadIdx.x;
    if (i < N) cnt[i] = 1;
}
__global__ void hist_k(int* cnt, const int* __restrict__ dst, int E) {
    int e = blockIdx.x * blockDim.x + threadIdx.x;
    if (e < E) atomicAdd(&cnt[dst[e]], 1);
}
__global__ void scanA_k(const int* __restrict__ cnt, int* bsum, int N) {
    __shared__ int sm[256];
    int gi = blockIdx.x * 256 + threadIdx.x;
    int v = (gi < N) ? cnt[gi] : 0;
    sm[threadIdx.x] = v; __syncthreads();
    for (int off = 128; off; off >>= 1) {
        if (threadIdx.x < off) sm[threadIdx.x] += sm[threadIdx.x + off];
        __syncthreads();
    }
    if (threadIdx.x == 0) bsum[blockIdx.x] = sm[0];
}
__global__ void scanB_k(const int* __restrict__ bsum, int* boff, int nb) {
    __shared__ int sm[256];
    int t = threadIdx.x;
    int v = (t < nb) ? bsum[t] : 0;
    sm[t] = v; __syncthreads();
    #pragma unroll
    for (int off = 1; off < 256; off <<= 1) {
        int x = (t >= off) ? sm[t - off] : 0;
        __syncthreads();
        sm[t] += x;
        __syncthreads();
    }
    if (t < nb) boff[t] = sm[t] - v;
}
__global__ void scanC_k(const int* __restrict__ cnt, const int* __restrict__ boff,
                        int* row, int* cur, int N) {
    __shared__ int sm[256];
    int t = threadIdx.x;
    int gi = blockIdx.x * 256 + t;
    int v = (gi < N) ? cnt[gi] : 0;
    sm[t] = v; __syncthreads();
    #pragma unroll
    for (int off = 1; off < 256; off <<= 1) {
        int x = (t >= off) ? sm[t - off] : 0;
        __syncthreads();
        sm[t] += x;
        __syncthreads();
    }
    int excl = boff[blockIdx.x] + sm[t] - v;
    if (gi < N) { row[gi] = excl; cur[gi] = excl; }
    if (gi == N - 1) row[N] = excl + v;
}
__global__ void scatter_k(const int* __restrict__ src, const int* __restrict__ dst,
                          int* cur, int* esrc, int E, int ET) {
    int e = blockIdx.x * blockDim.x + threadIdx.x;
    if (e >= ET) return;
    int s_, d_;
    if (e < E) { s_ = src[e]; d_ = dst[e]; } else { s_ = d_ = e - E; }
    int pos = atomicAdd(&cur[d_], 1);
    esrc[pos] = s_;
}

// ---------------- fused GAT aggregate, layer 1 (H=8, C=32): warp per dst ----
__global__ void gat8_k(const float* __restrict__ h1,
                       const float* __restrict__ as, const float* __restrict__ ad,
                       const int* __restrict__ row, const int* __restrict__ esrc,
                       const float* __restrict__ bias, float* __restrict__ out, int N) {
    int w = (blockIdx.x * blockDim.x + threadIdx.x) >> 5;
    int l = threadIdx.x & 31;
    if (w >= N) return;
    int hgrp = l >> 2;
    int rs = row[w], re = row[w + 1];
    float adh = ad[w * 8 + hgrp];

    float mx = -3.0e38f;
    int s = esrc[rs];
    for (int i = rs; i < re; i++) {
        int sn = (i + 1 < re) ? esrc[i + 1] : 0;
        float v = lrelu(__ldg(as + s * 8 + hgrp) + adh);
        mx = fmaxf(mx, v);
        s = sn;
    }
    float sum = 0.f;
    float4 acc0 = make_float4(0.f, 0.f, 0.f, 0.f);
    float4 acc1 = make_float4(0.f, 0.f, 0.f, 0.f);
    s = esrc[rs];
    for (int i = rs; i < re; i++) {
        int sn = (i + 1 < re) ? esrc[i + 1] : 0;
        float v = lrelu(__ldg(as + s * 8 + hgrp) + adh);
        float ex = expf(v - mx);
        sum += ex;
        const float4* hp = (const float4*)(h1 + (size_t)s * 256);
        float4 a = hp[2 * l], b = hp[2 * l + 1];
        acc0.x += ex * a.x; acc0.y += ex * a.y; acc0.z += ex * a.z; acc0.w += ex * a.w;
        acc1.x += ex * b.x; acc1.y += ex * b.y; acc1.z += ex * b.z; acc1.w += ex * b.w;
        s = sn;
    }
    float inv = 1.f / (sum + 1e-16f);
    float4 b0 = ((const float4*)bias)[2 * l];
    float4 b1 = ((const float4*)bias)[2 * l + 1];
    float4 o0 = make_float4(acc0.x * inv + b0.x, acc0.y * inv + b0.y,
                            acc0.z * inv + b0.z, acc0.w * inv + b0.w);
    float4 o1 = make_float4(acc1.x * inv + b1.x, acc1.y * inv + b1.y,
                            acc1.z * inv + b1.z, acc1.w * inv + b1.w);
    float4* op = (float4*)(out + (size_t)w * 256);
    op[2 * l] = o0; op[2 * l + 1] = o1;
}

// ---------------- fused GAT aggregate, layer 2 (H=1, C=32): warp per dst ----
__global__ void gat1_k(const float* __restrict__ h2,
                       const float* __restrict__ as, const float* __restrict__ ad,
                       const int* __restrict__ row, const int* __restrict__ esrc,
                       const float* __restrict__ bias, float* __restrict__ out, int N) {
    int w = (blockIdx.x * blockDim.x + threadIdx.x) >> 5;
    int l = threadIdx.x & 31;
    if (w >= N) return;
    int rs = row[w], re = row[w + 1];
    float adh = ad[w];

    float mx = -3.0e38f;
    int s = esrc[rs];
    for (int i = rs; i < re; i++) {
        int sn = (i + 1 < re) ? esrc[i + 1] : 0;
        float v = lrelu(__ldg(as + s) + adh);
        mx = fmaxf(mx, v);
        s = sn;
    }
    float sum = 0.f, acc = 0.f;
    s = esrc[rs];
    for (int i = rs; i < re; i++) {
        int sn = (i + 1 < re) ? esrc[i + 1] : 0;
        float v = lrelu(__ldg(as + s) + adh);
        float ex = expf(v - mx);
        sum += ex;
        acc += ex * __ldg(h2 + (size_t)s * 32 + l);
        s = sn;
    }
    out[(size_t)w * 32 + l] = acc / (sum + 1e-16f) + bias[l];
}

// ---------------- launch ----------------
extern "C" void kernel_launch(void* const* d_in, const int* in_sizes, int n_in,
                              void* d_out, int out_size) {
    const float* x   = (const float*)d_in[0];
    const int*   ei  = (const int*)d_in[1];
    const float* W1  = (const float*)d_in[2];
    const float* aS1 = (const float*)d_in[3];
    const float* aD1 = (const float*)d_in[4];
    const float* b1  = (const float*)d_in[5];
    const float* W2  = (const float*)d_in[6];
    const float* aS2 = (const float*)d_in[7];
    const float* aD2 = (const float*)d_in[8];
    const float* b2  = (const float*)d_in[9];
    const float* Wd  = (const float*)d_in[10];
    const float* bd  = (const float*)d_in[11];
    float* out = (float*)d_out;

    int N  = in_sizes[0] / 128;
    int E  = in_sizes[1] / 2;
    int ET = E + N;
    const int* src = ei;
    const int* dst = ei + E;

    float *h1, *o1, *as1, *ad1, *h2, *z, *as2, *ad2;
    int *cnt, *row, *cur, *bsum, *boff, *esrc;
    cudaGetSymbolAddress((void**)&h1,   g_h1);
    cudaGetSymbolAddress((void**)&o1,   g_o1);
    cudaGetSymbolAddress((void**)&as1,  g_as1);
    cudaGetSymbolAddress((void**)&ad1,  g_ad1);
    cudaGetSymbolAddress((void**)&h2,   g_h2);
    cudaGetSymbolAddress((void**)&z,    g_z);
    cudaGetSymbolAddress((void**)&as2,  g_as2);
    cudaGetSymbolAddress((void**)&ad2,  g_ad2);
    cudaGetSymbolAddress((void**)&cnt,  g_cnt);
    cudaGetSymbolAddress((void**)&row,  g_row);
    cudaGetSymbolAddress((void**)&cur,  g_cur);
    cudaGetSymbolAddress((void**)&bsum, g_bsum);
    cudaGetSymbolAddress((void**)&boff, g_boff);
    cudaGetSymbolAddress((void**)&esrc, g_esrc);

    const int TB = 256;
    int mb = (N + 127) / 128;
    int nb = (N + 255) / 256;

    init_cnt_k<<<nb, TB>>>(cnt, N);                                    // 1
    hist_k<<<(E + TB - 1) / TB, TB>>>(cnt, dst, E);                    // 2
    scanA_k<<<nb, TB>>>(cnt, bsum, N);                                 // 3
    // GEMM1 + fused alpha8 (profiled as launch 4)
    gemm_k<<<dim3(4, mb), TB>>>(x, W1, nullptr, h1, N, 256, 128, 0,
                                aS1, aD1, as1, ad1, 8);                // 4
    scanB_k<<<1, TB>>>(bsum, boff, nb);                                // 5
    scanC_k<<<nb, TB>>>(cnt, boff, row, cur, N);                       // 6
    scatter_k<<<(ET + TB - 1) / TB, TB>>>(src, dst, cur, esrc, E, ET); // 7

    // ===== Layer 1 aggregate =====
    gat8_k<<<(N * 32 + TB - 1) / TB, TB>>>(h1, as1, ad1, row, esrc, b1, o1, N); // 8

    // ===== Layer 2: GEMM2 (relu fused, alpha1 fused) =====
    gemm_k<<<dim3(1, mb), TB>>>(o1, W2, nullptr, h2, N, 32, 256, 1,
                                aS2, aD2, as2, ad2, 1);                // 9
    gat1_k<<<(N * 32 + TB - 1) / TB, TB>>>(h2, as2, ad2, row, esrc, b2, z, N);  // 10

    // ===== Decoder =====
    gemm_k<<<dim3(2, mb), TB>>>(z, Wd, bd, out, N, 128, 32, 0,
                                nullptr, nullptr, nullptr, nullptr, 0); // 11
}

// round 13
// speedup vs baseline: 1.0867x; 1.0867x over previous
#include <cuda_runtime.h>
#include <cuda_fp16.h>
#include <math.h>

static const int MAXN = 50000;
static const int MAXE = 800000 + MAXN;

// ---------------- scratch ----------------
__device__ __half g_h1h[MAXN * 256];   // layer1 features, fp16 (gather-only)
__device__ float  g_o1[MAXN * 256];
__device__ float  g_as1[MAXN * 8];
__device__ float  g_ad1[MAXN * 8];
__device__ __half g_h2h[MAXN * 32];    // layer2 features, fp16 (gather-only)
__device__ float  g_z[MAXN * 32];
__device__ float  g_as2[MAXN];
__device__ float  g_ad2[MAXN];
__device__ int    g_cnt[MAXN];
__device__ int    g_row[MAXN + 1];
__device__ int    g_cur[MAXN];
__device__ int    g_bsum[256];
__device__ int    g_boff[256];
__device__ int    g_esrc[MAXE];

__device__ __forceinline__ float lrelu(float v) { return v > 0.f ? v : 0.2f * v; }

// ---------------- GEMM 128x64 SIMT + fused alpha epilogue + optional fp16 C ----
// C[M,N] = A[M,K] @ B[K,N] (+bias), optional relu(A). halfC: store C as __half.
// If als != nullptr: per-row per-head (32-col) dots with aS/aD ([H,32]) reduced
// across tx-octets -> als/ald ([M,H]); head = n0/32 + tx/8 (exact fp32 accs).
__global__ void gemm_k(const float* __restrict__ A, const float* __restrict__ B,
                       const float* __restrict__ bias, void* __restrict__ Cv,
                       int M, int N, int K, int reluA, int halfC,
                       const float* __restrict__ aS, const float* __restrict__ aD,
                       float* __restrict__ als, float* __restrict__ ald, int H) {
    __shared__ float As[16][132];
    __shared__ float Bs[16][64];
    int tid = threadIdx.x;
    int ty = tid >> 4;
    int tx = tid & 15;
    int m0 = blockIdx.y * 128;
    int n0 = blockIdx.x * 64;
    float acc[8][4] = {};

    for (int k0 = 0; k0 < K; k0 += 16) {
        #pragma unroll
        for (int i = 0; i < 2; i++) {
            int L = tid + 256 * i;
            int row = L >> 2, q = (L & 3) << 2;
            float4 v = make_float4(0.f, 0.f, 0.f, 0.f);
            if (m0 + row < M) {
                v = *(const float4*)(A + (size_t)(m0 + row) * K + k0 + q);
                if (reluA) {
                    v.x = fmaxf(v.x, 0.f); v.y = fmaxf(v.y, 0.f);
                    v.z = fmaxf(v.z, 0.f); v.w = fmaxf(v.w, 0.f);
                }
            }
            As[q + 0][row] = v.x; As[q + 1][row] = v.y;
            As[q + 2][row] = v.z; As[q + 3][row] = v.w;
        }
        {
            int kl = tid >> 4, g = (tid & 15) << 2;
            float4 v = make_float4(0.f, 0.f, 0.f, 0.f);
            if (n0 + g < N)
                v = *(const float4*)(B + (size_t)(k0 + kl) * N + n0 + g);
            *(float4*)&Bs[kl][g] = v;
        }
        __syncthreads();
        #pragma unroll
        for (int kk = 0; kk < 16; kk++) {
            float a[8], b[4];
            *(float4*)&a[0] = *(const float4*)&As[kk][ty * 8];
            *(float4*)&a[4] = *(const float4*)&As[kk][ty * 8 + 4];
            *(float4*)&b[0] = *(const float4*)&Bs[kk][tx * 4];
            #pragma unroll
            for (int i = 0; i < 8; i++)
                #pragma unroll
                for (int j = 0; j < 4; j++)
                    acc[i][j] += a[i] * b[j];
        }
        __syncthreads();
    }
    int colb = n0 + tx * 4;
    if (colb < N) {
        float4 bv = make_float4(0.f, 0.f, 0.f, 0.f);
        if (bias) bv = *(const float4*)(bias + colb);
        #pragma unroll
        for (int i = 0; i < 8; i++) {
            int row = m0 + ty * 8 + i;
            if (row >= M) break;
            float4 v = make_float4(acc[i][0] + bv.x, acc[i][1] + bv.y,
                                   acc[i][2] + bv.z, acc[i][3] + bv.w);
            if (halfC) {
                __half2 p0 = __floats2half2_rn(v.x, v.y);
                __half2 p1 = __floats2half2_rn(v.z, v.w);
                uint2 pk;
                pk.x = *(unsigned*)&p0; pk.y = *(unsigned*)&p1;
                *(uint2*)((__half*)Cv + (size_t)row * N + colb) = pk;
            } else {
                *(float4*)((float*)Cv + (size_t)row * N + colb) = v;
            }
        }
    }
    // fused alpha epilogue (exact fp32 accs): head = n0/32 + tx/8
    if (als) {
        int hl = tx >> 3;
        int head = (n0 >> 5) + hl;
        float4 cs = make_float4(0.f, 0.f, 0.f, 0.f), cd = cs;
        if (head < H) {
            cs = ((const float4*)aS)[head * 8 + (tx & 7)];
            cd = ((const float4*)aD)[head * 8 + (tx & 7)];
        }
        #pragma unroll
        for (int i = 0; i < 8; i++) {
            float ps = acc[i][0] * cs.x + acc[i][1] * cs.y + acc[i][2] * cs.z + acc[i][3] * cs.w;
            float pd = acc[i][0] * cd.x + acc[i][1] * cd.y + acc[i][2] * cd.z + acc[i][3] * cd.w;
            #pragma unroll
            for (int off = 4; off; off >>= 1) {
                ps += __shfl_xor_sync(0xffffffffu, ps, off);
                pd += __shfl_xor_sync(0xffffffffu, pd, off);
            }
            int row = m0 + ty * 8 + i;
            if ((tx & 7) == 0 && head < H && row < M) {
                als[(size_t)row * H + head] = ps;
                ald[(size_t)row * H + head] = pd;
            }
        }
    }
}

// ---------------- CSR build ----------------
__global__ void init_cnt_k(int* cnt, int N) {
    int i = blockIdx.x * blockDim.x + threadIdx.x;
    if (i < N) cnt[i] = 1;
}
__global__ void hist_k(int* cnt, const int* __restrict__ dst, int E) {
    int e = blockIdx.x * blockDim.x + threadIdx.x;
    if (e < E) atomicAdd(&cnt[dst[e]], 1);
}
__global__ void scanA_k(const int* __restrict__ cnt, int* bsum, int N) {
    __shared__ int sm[256];
    int gi = blockIdx.x * 256 + threadIdx.x;
    int v = (gi < N) ? cnt[gi] : 0;
    sm[threadIdx.x] = v; __syncthreads();
    for (int off = 128; off; off >>= 1) {
        if (threadIdx.x < off) sm[threadIdx.x] += sm[threadIdx.x + off];
        __syncthreads();
    }
    if (threadIdx.x == 0) bsum[blockIdx.x] = sm[0];
}
__global__ void scanB_k(const int* __restrict__ bsum, int* boff, int nb) {
    __shared__ int sm[256];
    int t = threadIdx.x;
    int v = (t < nb) ? bsum[t] : 0;
    sm[t] = v; __syncthreads();
    #pragma unroll
    for (int off = 1; off < 256; off <<= 1) {
        int x = (t >= off) ? sm[t - off] : 0;
        __syncthreads();
        sm[t] += x;
        __syncthreads();
    }
    if (t < nb) boff[t] = sm[t] - v;
}
__global__ void scanC_k(const int* __restrict__ cnt, const int* __restrict__ boff,
                        int* row, int* cur, int N) {
    __shared__ int sm[256];
    int t = threadIdx.x;
    int gi = blockIdx.x * 256 + t;
    int v = (gi < N) ? cnt[gi] : 0;
    sm[t] = v; __syncthreads();
    #pragma unroll
    for (int off = 1; off < 256; off <<= 1) {
        int x = (t >= off) ? sm[t - off] : 0;
        __syncthreads();
        sm[t] += x;
        __syncthreads();
    }
    int excl = boff[blockIdx.x] + sm[t] - v;
    if (gi < N) { row[gi] = excl; cur[gi] = excl; }
    if (gi == N - 1) row[N] = excl + v;
}
__global__ void scatter_k(const int* __restrict__ src, const int* __restrict__ dst,
                          int* cur, int* esrc, int E, int ET) {
    int e = blockIdx.x * blockDim.x + threadIdx.x;
    if (e >= ET) return;
    int s_, d_;
    if (e < E) { s_ = src[e]; d_ = dst[e]; } else { s_ = d_ = e - E; }
    int pos = atomicAdd(&cur[d_], 1);
    esrc[pos] = s_;
}

// ---------------- fused GAT aggregate, layer 1 (H=8, C=32), fp16 gather ----
// Lane l covers cols 8l..8l+7 (one uint4 = 8 halves), all in head l>>2.
__global__ void gat8_k(const __half* __restrict__ h1,
                       const float* __restrict__ as, const float* __restrict__ ad,
                       const int* __restrict__ row, const int* __restrict__ esrc,
                       const float* __restrict__ bias, float* __restrict__ out, int N) {
    int w = (blockIdx.x * blockDim.x + threadIdx.x) >> 5;
    int l = threadIdx.x & 31;
    if (w >= N) return;
    int hgrp = l >> 2;
    int rs = row[w], re = row[w + 1];
    float adh = ad[w * 8 + hgrp];

    float mx = -3.0e38f;
    int s = esrc[rs];
    for (int i = rs; i < re; i++) {
        int sn = (i + 1 < re) ? esrc[i + 1] : 0;
        float v = lrelu(__ldg(as + s * 8 + hgrp) + adh);
        mx = fmaxf(mx, v);
        s = sn;
    }
    float sum = 0.f;
    float acc[8] = {};
    s = esrc[rs];
    for (int i = rs; i < re; i++) {
        int sn = (i + 1 < re) ? esrc[i + 1] : 0;
        float v = lrelu(__ldg(as + s * 8 + hgrp) + adh);
        float ex = expf(v - mx);
        sum += ex;
        uint4 raw = ((const uint4*)(h1 + (size_t)s * 256))[l];
        __half2* hh = (__half2*)&raw;
        float2 f0 = __half22float2(hh[0]);
        float2 f1 = __half22float2(hh[1]);
        float2 f2 = __half22float2(hh[2]);
        float2 f3 = __half22float2(hh[3]);
        acc[0] += ex * f0.x; acc[1] += ex * f0.y;
        acc[2] += ex * f1.x; acc[3] += ex * f1.y;
        acc[4] += ex * f2.x; acc[5] += ex * f2.y;
        acc[6] += ex * f3.x; acc[7] += ex * f3.y;
        s = sn;
    }
    float inv = 1.f / (sum + 1e-16f);
    float4 b0 = ((const float4*)bias)[2 * l];
    float4 b1 = ((const float4*)bias)[2 * l + 1];
    float4 o0 = make_float4(acc[0] * inv + b0.x, acc[1] * inv + b0.y,
                            acc[2] * inv + b0.z, acc[3] * inv + b0.w);
    float4 o1 = make_float4(acc[4] * inv + b1.x, acc[5] * inv + b1.y,
                            acc[6] * inv + b1.z, acc[7] * inv + b1.w);
    float4* op = (float4*)(out + (size_t)w * 256 + 8 * l);
    op[0] = o0; op[1] = o1;
}

// ---------------- fused GAT aggregate, layer 2 (H=1, C=32), fp16 gather ----
__global__ void gat1_k(const __half* __restrict__ h2,
                       const float* __restrict__ as, const float* __restrict__ ad,
                       const int* __restrict__ row, const int* __restrict__ esrc,
                       const float* __restrict__ bias, float* __restrict__ out, int N) {
    int w = (blockIdx.x * blockDim.x + threadIdx.x) >> 5;
    int l = threadIdx.x & 31;
    if (w >= N) return;
    int rs = row[w], re = row[w + 1];
    float adh = ad[w];

    float mx = -3.0e38f;
    int s = esrc[rs];
    for (int i = rs; i < re; i++) {
        int sn = (i + 1 < re) ? esrc[i + 1] : 0;
        float v = lrelu(__ldg(as + s) + adh);
        mx = fmaxf(mx, v);
        s = sn;
    }
    float sum = 0.f, acc = 0.f;
    s = esrc[rs];
    for (int i = rs; i < re; i++) {
        int sn = (i + 1 < re) ? esrc[i + 1] : 0;
        float v = lrelu(__ldg(as + s) + adh);
        float ex = expf(v - mx);
        sum += ex;
        acc += ex * __half2float(__ldg(h2 + (size_t)s * 32 + l));
        s = sn;
    }
    out[(size_t)w * 32 + l] = acc / (sum + 1e-16f) + bias[l];
}

// ---------------- launch ----------------
extern "C" void kernel_launch(void* const* d_in, const int* in_sizes, int n_in,
                              void* d_out, int out_size) {
    const float* x   = (const float*)d_in[0];
    const int*   ei  = (const int*)d_in[1];
    const float* W1  = (const float*)d_in[2];
    const float* aS1 = (const float*)d_in[3];
    const float* aD1 = (const float*)d_in[4];
    const float* b1  = (const float*)d_in[5];
    const float* W2  = (const float*)d_in[6];
    const float* aS2 = (const float*)d_in[7];
    const float* aD2 = (const float*)d_in[8];
    const float* b2  = (const float*)d_in[9];
    const float* Wd  = (const float*)d_in[10];
    const float* bd  = (const float*)d_in[11];
    float* out = (float*)d_out;

    int N  = in_sizes[0] / 128;
    int E  = in_sizes[1] / 2;
    int ET = E + N;
    const int* src = ei;
    const int* dst = ei + E;

    float *o1, *as1, *ad1, *z, *as2, *ad2;
    __half *h1h, *h2h;
    int *cnt, *row, *cur, *bsum, *boff, *esrc;
    cudaGetSymbolAddress((void**)&h1h,  g_h1h);
    cudaGetSymbolAddress((void**)&o1,   g_o1);
    cudaGetSymbolAddress((void**)&as1,  g_as1);
    cudaGetSymbolAddress((void**)&ad1,  g_ad1);
    cudaGetSymbolAddress((void**)&h2h,  g_h2h);
    cudaGetSymbolAddress((void**)&z,    g_z);
    cudaGetSymbolAddress((void**)&as2,  g_as2);
    cudaGetSymbolAddress((void**)&ad2,  g_ad2);
    cudaGetSymbolAddress((void**)&cnt,  g_cnt);
    cudaGetSymbolAddress((void**)&row,  g_row);
    cudaGetSymbolAddress((void**)&cur,  g_cur);
    cudaGetSymbolAddress((void**)&bsum, g_bsum);
    cudaGetSymbolAddress((void**)&boff, g_boff);
    cudaGetSymbolAddress((void**)&esrc, g_esrc);

    const int TB = 256;
    int mb = (N + 127) / 128;
    int nb = (N + 255) / 256;

    init_cnt_k<<<nb, TB>>>(cnt, N);                                    // 1
    hist_k<<<(E + TB - 1) / TB, TB>>>(cnt, dst, E);                    // 2
    scanA_k<<<nb, TB>>>(cnt, bsum, N);                                 // 3
    // GEMM1 + fused alpha8, fp16 C (profiled as launch 4)
    gemm_k<<<dim3(4, mb), TB>>>(x, W1, nullptr, h1h, N, 256, 128, 0, 1,
                                aS1, aD1, as1, ad1, 8);                // 4
    scanB_k<<<1, TB>>>(bsum, boff, nb);                                // 5
    scanC_k<<<nb, TB>>>(cnt, boff, row, cur, N);                       // 6
    scatter_k<<<(ET + TB - 1) / TB, TB>>>(src, dst, cur, esrc, E, ET); // 7

    // ===== Layer 1 aggregate (fp16 gather) =====
    gat8_k<<<(N * 32 + TB - 1) / TB, TB>>>(h1h, as1, ad1, row, esrc, b1, o1, N); // 8

    // ===== Layer 2: GEMM2 (relu fused, alpha1 fused, fp16 C) =====
    gemm_k<<<dim3(1, mb), TB>>>(o1, W2, nullptr, h2h, N, 32, 256, 1, 1,
                                aS2, aD2, as2, ad2, 1);                // 9
    gat1_k<<<(N * 32 + TB - 1) / TB, TB>>>(h2h, as2, ad2, row, esrc, b2, z, N);  // 10

    // ===== Decoder (fp32) =====
    gemm_k<<<dim3(2, mb), TB>>>(z, Wd, bd, out, N, 128, 32, 0, 0,
                                nullptr, nullptr, nullptr, nullptr, 0); // 11
}

// round 14
// speedup vs baseline: 1.1525x; 1.0605x over previous
#include <cuda_runtime.h>
#include <cuda_fp16.h>
#include <mma.h>
#include <math.h>
#include <stdint.h>

using namespace nvcuda;

static const int MAXN = 50000;
static const int MAXE = 800000 + MAXN;

// ---------------- scratch ----------------
__device__ __half g_h1h[MAXN * 256];   // layer1 features, fp16 (gather-only)
__device__ float  g_o1[MAXN * 256];
__device__ float  g_as1[MAXN * 8];
__device__ float  g_ad1[MAXN * 8];
__device__ __half g_h2h[MAXN * 32];    // layer2 features, fp16
__device__ float  g_z[MAXN * 32];
__device__ float  g_as2[MAXN];
__device__ float  g_ad2[MAXN];
__device__ int    g_cnt[MAXN];
__device__ int    g_row[MAXN + 1];
__device__ int    g_cur[MAXN];
__device__ int    g_bsum[256];
__device__ int    g_boff[256];
__device__ int    g_esrc[MAXE];
__device__ __half g_xh[MAXN * 128];    // x in fp16
__device__ __half g_wthi[256 * 128];   // W1^T hi
__device__ __half g_wtlo[256 * 128];   // W1^T lo

__device__ __forceinline__ float lrelu(float v) { return v > 0.f ? v : 0.2f * v; }

// ================= GEMM1 wmma fp16 2-pass + fused alpha8, fp16 out =========
// h1[M,256] = x[M,128] @ W1[128,256]; x fp16, W1t = whi + wlo (fp16 pair, W
// side exact to ~2^-22). acc = xh*whi + xh*wlo, fp32 accumulate.
// CTA 128x128 tile (4 heads), 16 warps 32x32, 2 CTAs/SM (smem 102KB).
static const int LDM = 136;
static const int CLD = 132;
static const int WSM_TOTAL = 3 * 128 * LDM * 2;   // 104448

__global__ __launch_bounds__(512, 2)
void gemm1_wmma_k(const __half* __restrict__ xh,
                  const __half* __restrict__ wthi, const __half* __restrict__ wtlo,
                  const float* __restrict__ aS1, const float* __restrict__ aD1,
                  __half* __restrict__ outh, float* __restrict__ as, float* __restrict__ ad,
                  int M) {
    extern __shared__ char smraw[];
    __half* Ah = (__half*)smraw;
    __half* Bh = Ah + 128 * LDM;
    __half* Bl = Bh + 128 * LDM;
    float* Csf = (float*)smraw;                   // epilogue reuse (67584 <= 104448)
    int tid = threadIdx.x, wid = tid >> 5, lane = tid & 31;
    int m0 = blockIdx.y * 128, n0 = blockIdx.x * 128;

    for (int idx = tid; idx < 128 * 16; idx += 512) {
        int r = idx >> 4, c = idx & 15;
        uint4 v = make_uint4(0u, 0u, 0u, 0u);
        if (m0 + r < M) v = ((const uint4*)xh)[(size_t)(m0 + r) * 16 + c];
        ((uint4*)(Ah + r * LDM))[c] = v;
    }
    for (int idx = tid; idx < 128 * 16; idx += 512) {
        int r = idx >> 4, c = idx & 15;
        ((uint4*)(Bh + r * LDM))[c] = ((const uint4*)wthi)[(size_t)(n0 + r) * 16 + c];
        ((uint4*)(Bl + r * LDM))[c] = ((const uint4*)wtlo)[(size_t)(n0 + r) * 16 + c];
    }
    __syncthreads();

    int wr = wid & 3, wc = wid >> 2;   // warp tile rows wr*32..+31, cols wc*32..+31
    wmma::fragment<wmma::accumulator, 16, 16, 16, float> acc[2][2];
    #pragma unroll
    for (int i = 0; i < 2; i++)
        #pragma unroll
        for (int j = 0; j < 2; j++) wmma::fill_fragment(acc[i][j], 0.f);

    #pragma unroll
    for (int p = 0; p < 2; p++) {
        const __half* Bb = p ? Bl : Bh;
        #pragma unroll
        for (int k = 0; k < 128; k += 16) {
            wmma::fragment<wmma::matrix_a, 16, 16, 16, __half, wmma::row_major> af[2];
            wmma::fragment<wmma::matrix_b, 16, 16, 16, __half, wmma::col_major> bf[2];
            #pragma unroll
            for (int i = 0; i < 2; i++)
                wmma::load_matrix_sync(af[i], Ah + (wr * 32 + i * 16) * LDM + k, LDM);
            #pragma unroll
            for (int j = 0; j < 2; j++)
                wmma::load_matrix_sync(bf[j], Bb + (wc * 32 + j * 16) * LDM + k, LDM);
            #pragma unroll
            for (int i = 0; i < 2; i++)
                #pragma unroll
                for (int j = 0; j < 2; j++)
                    wmma::mma_sync(acc[i][j], af[i], bf[j], acc[i][j]);
        }
    }
    __syncthreads();   // tiles no longer needed

    #pragma unroll
    for (int i = 0; i < 2; i++)
        #pragma unroll
        for (int j = 0; j < 2; j++)
            wmma::store_matrix_sync(Csf + (wr * 32 + i * 16) * CLD + wc * 32 + j * 16,
                                    acc[i][j], CLD, wmma::mem_row_major);
    __syncthreads();

    // fused alpha: CTA heads hb..hb+3; warp w -> rows w*8..+7 (validated in R11)
    {
        int hb = n0 >> 5;
        int hl = lane >> 3, k4 = lane & 7;
        float4 cs = ((const float4*)aS1)[(hb + hl) * 8 + k4];
        float4 cd = ((const float4*)aD1)[(hb + hl) * 8 + k4];
        #pragma unroll
        for (int rr = 0; rr < 8; rr++) {
            int r = wid * 8 + rr;
            float4 v = *(float4*)&Csf[r * CLD + hl * 32 + k4 * 4];
            float ps = v.x * cs.x + v.y * cs.y + v.z * cs.z + v.w * cs.w;
            float pd = v.x * cd.x + v.y * cd.y + v.z * cd.z + v.w * cd.w;
            #pragma unroll
            for (int off = 4; off; off >>= 1) {
                ps += __shfl_xor_sync(0xffffffffu, ps, off);
                pd += __shfl_xor_sync(0xffffffffu, pd, off);
            }
            int gr = m0 + r;
            if (k4 == 0 && gr < M) {
                as[gr * 8 + hb + hl] = ps;
                ad[gr * 8 + hb + hl] = pd;
            }
        }
    }
    // h1 store as fp16 (coalesced uint4 = 8 halves)
    for (int idx = tid; idx < 128 * 16; idx += 512) {
        int r = idx >> 4, c8 = idx & 15;
        if (m0 + r >= M) continue;
        float4 v0 = *(float4*)&Csf[r * CLD + c8 * 8];
        float4 v1 = *(float4*)&Csf[r * CLD + c8 * 8 + 4];
        __half2 p0 = __floats2half2_rn(v0.x, v0.y);
        __half2 p1 = __floats2half2_rn(v0.z, v0.w);
        __half2 p2 = __floats2half2_rn(v1.x, v1.y);
        __half2 p3 = __floats2half2_rn(v1.z, v1.w);
        uint4 pk;
        pk.x = *(unsigned*)&p0; pk.y = *(unsigned*)&p1;
        pk.z = *(unsigned*)&p2; pk.w = *(unsigned*)&p3;
        *(uint4*)(outh + (size_t)(m0 + r) * 256 + n0 + c8 * 8) = pk;
    }
}

// ---------------- merged conversions (x -> fp16; W1t -> fp16 hi/lo) --------
__global__ void conv_k(const float4* __restrict__ x4, uint2* __restrict__ xh, int n4,
                       const float* __restrict__ W1,
                       __half* __restrict__ whi, __half* __restrict__ wlo) {
    int nxb = (n4 + 255) >> 8;
    if ((int)blockIdx.x < nxb) {
        int i = blockIdx.x * 256 + threadIdx.x;
        if (i >= n4) return;
        float4 v = x4[i];
        __half2 p0 = __floats2half2_rn(v.x, v.y);
        __half2 p1 = __floats2half2_rn(v.z, v.w);
        uint2 pk;
        pk.x = *(unsigned*)&p0; pk.y = *(unsigned*)&p1;
        xh[i] = pk;
    } else {
        int i = (blockIdx.x - nxb) * 256 + threadIdx.x;   // Wt[n,k] <- W[k,n]
        if (i >= 256 * 128) return;
        int n = i >> 7, k = i & 127;
        float v = W1[k * 256 + n];
        __half h = __float2half_rn(v);
        whi[i] = h;
        wlo[i] = __float2half_rn(v - __half2float(h));
    }
}

// ---------------- GEMM 128x64 SIMT + fused alpha + optional fp16 C ----------
__global__ void gemm_k(const float* __restrict__ A, const float* __restrict__ B,
                       const float* __restrict__ bias, void* __restrict__ Cv,
                       int M, int N, int K, int reluA, int halfC,
                       const float* __restrict__ aS, const float* __restrict__ aD,
                       float* __restrict__ als, float* __restrict__ ald, int H) {
    __shared__ float As[16][132];
    __shared__ float Bs[16][64];
    int tid = threadIdx.x;
    int ty = tid >> 4;
    int tx = tid & 15;
    int m0 = blockIdx.y * 128;
    int n0 = blockIdx.x * 64;
    float acc[8][4] = {};

    for (int k0 = 0; k0 < K; k0 += 16) {
        #pragma unroll
        for (int i = 0; i < 2; i++) {
            int L = tid + 256 * i;
            int row = L >> 2, q = (L & 3) << 2;
            float4 v = make_float4(0.f, 0.f, 0.f, 0.f);
            if (m0 + row < M) {
                v = *(const float4*)(A + (size_t)(m0 + row) * K + k0 + q);
                if (reluA) {
                    v.x = fmaxf(v.x, 0.f); v.y = fmaxf(v.y, 0.f);
                    v.z = fmaxf(v.z, 0.f); v.w = fmaxf(v.w, 0.f);
                }
            }
            As[q + 0][row] = v.x; As[q + 1][row] = v.y;
            As[q + 2][row] = v.z; As[q + 3][row] = v.w;
        }
        {
            int kl = tid >> 4, g = (tid & 15) << 2;
            float4 v = make_float4(0.f, 0.f, 0.f, 0.f);
            if (n0 + g < N)
                v = *(const float4*)(B + (size_t)(k0 + kl) * N + n0 + g);
            *(float4*)&Bs[kl][g] = v;
        }
        __syncthreads();
        #pragma unroll
        for (int kk = 0; kk < 16; kk++) {
            float a[8], b[4];
            *(float4*)&a[0] = *(const float4*)&As[kk][ty * 8];
            *(float4*)&a[4] = *(const float4*)&As[kk][ty * 8 + 4];
            *(float4*)&b[0] = *(const float4*)&Bs[kk][tx * 4];
            #pragma unroll
            for (int i = 0; i < 8; i++)
                #pragma unroll
                for (int j = 0; j < 4; j++)
                    acc[i][j] += a[i] * b[j];
        }
        __syncthreads();
    }
    int colb = n0 + tx * 4;
    if (colb < N) {
        float4 bv = make_float4(0.f, 0.f, 0.f, 0.f);
        if (bias) bv = *(const float4*)(bias + colb);
        #pragma unroll
        for (int i = 0; i < 8; i++) {
            int row = m0 + ty * 8 + i;
            if (row >= M) break;
            float4 v = make_float4(acc[i][0] + bv.x, acc[i][1] + bv.y,
                                   acc[i][2] + bv.z, acc[i][3] + bv.w);
            if (halfC) {
                __half2 p0 = __floats2half2_rn(v.x, v.y);
                __half2 p1 = __floats2half2_rn(v.z, v.w);
                uint2 pk;
                pk.x = *(unsigned*)&p0; pk.y = *(unsigned*)&p1;
                *(uint2*)((__half*)Cv + (size_t)row * N + colb) = pk;
            } else {
                *(float4*)((float*)Cv + (size_t)row * N + colb) = v;
            }
        }
    }
    if (als) {
        int hl = tx >> 3;
        int head = (n0 >> 5) + hl;
        float4 cs = make_float4(0.f, 0.f, 0.f, 0.f), cd = cs;
        if (head < H) {
            cs = ((const float4*)aS)[head * 8 + (tx & 7)];
            cd = ((const float4*)aD)[head * 8 + (tx & 7)];
        }
        #pragma unroll
        for (int i = 0; i < 8; i++) {
            float ps = acc[i][0] * cs.x + acc[i][1] * cs.y + acc[i][2] * cs.z + acc[i][3] * cs.w;
            float pd = acc[i][0] * cd.x + acc[i][1] * cd.y + acc[i][2] * cd.z + acc[i][3] * cd.w;
            #pragma unroll
            for (int off = 4; off; off >>= 1) {
                ps += __shfl_xor_sync(0xffffffffu, ps, off);
                pd += __shfl_xor_sync(0xffffffffu, pd, off);
            }
            int row = m0 + ty * 8 + i;
            if ((tx & 7) == 0 && head < H && row < M) {
                als[(size_t)row * H + head] = ps;
                ald[(size_t)row * H + head] = pd;
            }
        }
    }
}

// ---------------- CSR build ----------------
__global__ void init_cnt_k(int* cnt, int N) {
    int i = blockIdx.x * blockDim.x + threadIdx.x;
    if (i < N) cnt[i] = 1;
}
__global__ void hist_k(int* cnt, const int* __restrict__ dst, int E) {
    int e = blockIdx.x * blockDim.x + threadIdx.x;
    if (e < E) atomicAdd(&cnt[dst[e]], 1);
}
__global__ void scanA_k(const int* __restrict__ cnt, int* bsum, int N) {
    __shared__ int sm[256];
    int gi = blockIdx.x * 256 + threadIdx.x;
    int v = (gi < N) ? cnt[gi] : 0;
    sm[threadIdx.x] = v; __syncthreads();
    for (int off = 128; off; off >>= 1) {
        if (threadIdx.x < off) sm[threadIdx.x] += sm[threadIdx.x + off];
        __syncthreads();
    }
    if (threadIdx.x == 0) bsum[blockIdx.x] = sm[0];
}
__global__ void scanB_k(const int* __restrict__ bsum, int* boff, int nb) {
    __shared__ int sm[256];
    int t = threadIdx.x;
    int v = (t < nb) ? bsum[t] : 0;
    sm[t] = v; __syncthreads();
    #pragma unroll
    for (int off = 1; off < 256; off <<= 1) {
        int x = (t >= off) ? sm[t - off] : 0;
        __syncthreads();
        sm[t] += x;
        __syncthreads();
    }
    if (t < nb) boff[t] = sm[t] - v;
}
__global__ void scanC_k(const int* __restrict__ cnt, const int* __restrict__ boff,
                        int* row, int* cur, int N) {
    __shared__ int sm[256];
    int t = threadIdx.x;
    int gi = blockIdx.x * 256 + t;
    int v = (gi < N) ? cnt[gi] : 0;
    sm[t] = v; __syncthreads();
    #pragma unroll
    for (int off = 1; off < 256; off <<= 1) {
        int x = (t >= off) ? sm[t - off] : 0;
        __syncthreads();
        sm[t] += x;
        __syncthreads();
    }
    int excl = boff[blockIdx.x] + sm[t] - v;
    if (gi < N) { row[gi] = excl; cur[gi] = excl; }
    if (gi == N - 1) row[N] = excl + v;
}
__global__ void scatter_k(const int* __restrict__ src, const int* __restrict__ dst,
                          int* cur, int* esrc, int E, int ET) {
    int e = blockIdx.x * blockDim.x + threadIdx.x;
    if (e >= ET) return;
    int s_, d_;
    if (e < E) { s_ = src[e]; d_ = dst[e]; } else { s_ = d_ = e - E; }
    int pos = atomicAdd(&cur[d_], 1);
    esrc[pos] = s_;
}

// ---------------- fused GAT aggregate, layer 1 (H=8, C=32), fp16 gather ----
__global__ void gat8_k(const __half* __restrict__ h1,
                       const float* __restrict__ as, const float* __restrict__ ad,
                       const int* __restrict__ row, const int* __restrict__ esrc,
                       const float* __restrict__ bias, float* __restrict__ out, int N) {
    int w = (blockIdx.x * blockDim.x + threadIdx.x) >> 5;
    int l = threadIdx.x & 31;
    if (w >= N) return;
    int hgrp = l >> 2;
    int rs = row[w], re = row[w + 1];
    float adh = ad[w * 8 + hgrp];

    float mx = -3.0e38f;
    int s = esrc[rs];
    for (int i = rs; i < re; i++) {
        int sn = (i + 1 < re) ? esrc[i + 1] : 0;
        float v = lrelu(__ldg(as + s * 8 + hgrp) + adh);
        mx = fmaxf(mx, v);
        s = sn;
    }
    float sum = 0.f;
    float acc[8] = {};
    s = esrc[rs];
    for (int i = rs; i < re; i++) {
        int sn = (i + 1 < re) ? esrc[i + 1] : 0;
        float v = lrelu(__ldg(as + s * 8 + hgrp) + adh);
        float ex = expf(v - mx);
        sum += ex;
        uint4 raw = ((const uint4*)(h1 + (size_t)s * 256))[l];
        __half2* hh = (__half2*)&raw;
        float2 f0 = __half22float2(hh[0]);
        float2 f1 = __half22float2(hh[1]);
        float2 f2 = __half22float2(hh[2]);
        float2 f3 = __half22float2(hh[3]);
        acc[0] += ex * f0.x; acc[1] += ex * f0.y;
        acc[2] += ex * f1.x; acc[3] += ex * f1.y;
        acc[4] += ex * f2.x; acc[5] += ex * f2.y;
        acc[6] += ex * f3.x; acc[7] += ex * f3.y;
        s = sn;
    }
    float inv = 1.f / (sum + 1e-16f);
    float4 b0 = ((const float4*)bias)[2 * l];
    float4 b1 = ((const float4*)bias)[2 * l + 1];
    float4 o0 = make_float4(acc[0] * inv + b0.x, acc[1] * inv + b0.y,
                            acc[2] * inv + b0.z, acc[3] * inv + b0.w);
    float4 o1 = make_float4(acc[4] * inv + b1.x, acc[5] * inv + b1.y,
                            acc[6] * inv + b1.z, acc[7] * inv + b1.w);
    float4* op = (float4*)(out + (size_t)w * 256 + 8 * l);
    op[0] = o0; op[1] = o1;
}

// ---------------- fused GAT aggregate, layer 2 (H=1, C=32), fp16 gather ----
__global__ void gat1_k(const __half* __restrict__ h2,
                       const float* __restrict__ as, const float* __restrict__ ad,
                       const int* __restrict__ row, const int* __restrict__ esrc,
                       const float* __restrict__ bias, float* __restrict__ out, int N) {
    int w = (blockIdx.x * blockDim.x + threadIdx.x) >> 5;
    int l = threadIdx.x & 31;
    if (w >= N) return;
    int rs = row[w], re = row[w + 1];
    float adh = ad[w];

    float mx = -3.0e38f;
    int s = esrc[rs];
    for (int i = rs; i < re; i++) {
        int sn = (i + 1 < re) ? esrc[i + 1] : 0;
        float v = lrelu(__ldg(as + s) + adh);
        mx = fmaxf(mx, v);
        s = sn;
    }
    float sum = 0.f, acc = 0.f;
    s = esrc[rs];
    for (int i = rs; i < re; i++) {
        int sn = (i + 1 < re) ? esrc[i + 1] : 0;
        float v = lrelu(__ldg(as + s) + adh);
        float ex = expf(v - mx);
        sum += ex;
        acc += ex * __half2float(__ldg(h2 + (size_t)s * 32 + l));
        s = sn;
    }
    out[(size_t)w * 32 + l] = acc / (sum + 1e-16f) + bias[l];
}

// ---------------- launch ----------------
extern "C" void kernel_launch(void* const* d_in, const int* in_sizes, int n_in,
                              void* d_out, int out_size) {
    const float* x   = (const float*)d_in[0];
    const int*   ei  = (const int*)d_in[1];
    const float* W1  = (const float*)d_in[2];
    const float* aS1 = (const float*)d_in[3];
    const float* aD1 = (const float*)d_in[4];
    const float* b1  = (const float*)d_in[5];
    const float* W2  = (const float*)d_in[6];
    const float* aS2 = (const float*)d_in[7];
    const float* aD2 = (const float*)d_in[8];
    const float* b2  = (const float*)d_in[9];
    const float* Wd  = (const float*)d_in[10];
    const float* bd  = (const float*)d_in[11];
    float* out = (float*)d_out;

    int N  = in_sizes[0] / 128;
    int E  = in_sizes[1] / 2;
    int ET = E + N;
    const int* src = ei;
    const int* dst = ei + E;

    float *o1, *as1, *ad1, *z, *as2, *ad2;
    __half *h1h, *h2h, *xh, *wthi, *wtlo;
    int *cnt, *row, *cur, *bsum, *boff, *esrc;
    cudaGetSymbolAddress((void**)&h1h,  g_h1h);
    cudaGetSymbolAddress((void**)&o1,   g_o1);
    cudaGetSymbolAddress((void**)&as1,  g_as1);
    cudaGetSymbolAddress((void**)&ad1,  g_ad1);
    cudaGetSymbolAddress((void**)&h2h,  g_h2h);
    cudaGetSymbolAddress((void**)&z,    g_z);
    cudaGetSymbolAddress((void**)&as2,  g_as2);
    cudaGetSymbolAddress((void**)&ad2,  g_ad2);
    cudaGetSymbolAddress((void**)&cnt,  g_cnt);
    cudaGetSymbolAddress((void**)&row,  g_row);
    cudaGetSymbolAddress((void**)&cur,  g_cur);
    cudaGetSymbolAddress((void**)&bsum, g_bsum);
    cudaGetSymbolAddress((void**)&boff, g_boff);
    cudaGetSymbolAddress((void**)&esrc, g_esrc);
    cudaGetSymbolAddress((void**)&xh,   g_xh);
    cudaGetSymbolAddress((void**)&wthi, g_wthi);
    cudaGetSymbolAddress((void**)&wtlo, g_wtlo);

    cudaFuncSetAttribute(gemm1_wmma_k, cudaFuncAttributeMaxDynamicSharedMemorySize, WSM_TOTAL);

    const int TB = 256;
    int mb = (N + 127) / 128;
    int nb = (N + 255) / 256;
    int n4 = N * 32;
    int nxb = (n4 + 255) / 256;

    init_cnt_k<<<nb, TB>>>(cnt, N);                                    // 1
    hist_k<<<(E + TB - 1) / TB, TB>>>(cnt, dst, E);                    // 2
    conv_k<<<nxb + 128, TB>>>((const float4*)x, (uint2*)xh, n4,
                              W1, wthi, wtlo);                         // 3
    gemm1_wmma_k<<<dim3(2, mb), 512, WSM_TOTAL>>>(xh, wthi, wtlo,
                                                  aS1, aD1, h1h, as1, ad1, N); // 4 (profiled)
    scanA_k<<<nb, TB>>>(cnt, bsum, N);                                 // 5
    scanB_k<<<1, TB>>>(bsum, boff, nb);                                // 6
    scanC_k<<<nb, TB>>>(cnt, boff, row, cur, N);                       // 7
    scatter_k<<<(ET + TB - 1) / TB, TB>>>(src, dst, cur, esrc, E, ET); // 8

    // ===== Layer 1 aggregate (fp16 gather) =====
    gat8_k<<<(N * 32 + TB - 1) / TB, TB>>>(h1h, as1, ad1, row, esrc, b1, o1, N); // 9

    // ===== Layer 2: GEMM2 (relu fused, alpha1 fused, fp16 C) =====
    gemm_k<<<dim3(1, mb), TB>>>(o1, W2, nullptr, h2h, N, 32, 256, 1, 1,
                                aS2, aD2, as2, ad2, 1);                // 10
    gat1_k<<<(N * 32 + TB - 1) / TB, TB>>>(h2h, as2, ad2, row, esrc, b2, z, N);  // 11

    // ===== Decoder (fp32) =====
    gemm_k<<<dim3(2, mb), TB>>>(z, Wd, bd, out, N, 128, 32, 0, 0,
                                nullptr, nullptr, nullptr, nullptr, 0); // 12
}

// round 15
// speedup vs baseline: 1.3066x; 1.1338x over previous
#include <cuda_runtime.h>
#include <cuda_fp16.h>
#include <mma.h>
#include <math.h>
#include <stdint.h>

using namespace nvcuda;

static const int MAXN = 50000;
static const int MAXE = 800000 + MAXN;

// ---------------- scratch ----------------
__device__ __half g_h1h[MAXN * 256];   // layer1 features, fp16 (gather-only)
__device__ float  g_o1[MAXN * 256];
__device__ float  g_as1[MAXN * 8];
__device__ float  g_ad1[MAXN * 8];
__device__ __half g_h2h[MAXN * 32];    // layer2 features, fp16
__device__ float  g_z[MAXN * 32];
__device__ float  g_as2[MAXN];
__device__ float  g_ad2[MAXN];
__device__ int    g_cnt[MAXN];
__device__ int    g_row[MAXN + 1];
__device__ int    g_cur[MAXN];
__device__ int    g_bsum[256];
__device__ int    g_boff[256];
__device__ int    g_esrc[MAXE];
__device__ __half g_xh[MAXN * 128];    // x in fp16
__device__ __half g_wth[256 * 128];    // W1^T fp16

__device__ __forceinline__ float lrelu(float v) { return v > 0.f ? v : 0.2f * v; }

// ================= GEMM1 wmma fp16 single-pass + fused alpha8, fp16 out =====
// h1[M,256] = x[M,128] @ W1[128,256]; x, W1 fp16, fp32 accumulate.
// CTA 128x128 tile (4 heads), 16 warps 32x32, 2 CTAs/SM (smem 68KB).
static const int LDM = 136;
static const int CLD = 132;
static const int WSM_TOTAL = 2 * 128 * LDM * 2;   // 69632 (>= 128*132*4 = 67584)

__global__ __launch_bounds__(512, 2)
void gemm1_wmma_k(const __half* __restrict__ xh, const __half* __restrict__ wth,
                  const float* __restrict__ aS1, const float* __restrict__ aD1,
                  __half* __restrict__ outh, float* __restrict__ as, float* __restrict__ ad,
                  int M) {
    extern __shared__ char smraw[];
    __half* Ah = (__half*)smraw;
    __half* Bh = Ah + 128 * LDM;
    float* Csf = (float*)smraw;                   // epilogue reuse
    int tid = threadIdx.x, wid = tid >> 5, lane = tid & 31;
    int m0 = blockIdx.y * 128, n0 = blockIdx.x * 128;

    for (int idx = tid; idx < 128 * 16; idx += 512) {
        int r = idx >> 4, c = idx & 15;
        uint4 v = make_uint4(0u, 0u, 0u, 0u);
        if (m0 + r < M) v = ((const uint4*)xh)[(size_t)(m0 + r) * 16 + c];
        ((uint4*)(Ah + r * LDM))[c] = v;
    }
    for (int idx = tid; idx < 128 * 16; idx += 512) {
        int r = idx >> 4, c = idx & 15;
        ((uint4*)(Bh + r * LDM))[c] = ((const uint4*)wth)[(size_t)(n0 + r) * 16 + c];
    }
    __syncthreads();

    int wr = wid & 3, wc = wid >> 2;
    wmma::fragment<wmma::accumulator, 16, 16, 16, float> acc[2][2];
    #pragma unroll
    for (int i = 0; i < 2; i++)
        #pragma unroll
        for (int j = 0; j < 2; j++) wmma::fill_fragment(acc[i][j], 0.f);

    #pragma unroll
    for (int k = 0; k < 128; k += 16) {
        wmma::fragment<wmma::matrix_a, 16, 16, 16, __half, wmma::row_major> af[2];
        wmma::fragment<wmma::matrix_b, 16, 16, 16, __half, wmma::col_major> bf[2];
        #pragma unroll
        for (int i = 0; i < 2; i++)
            wmma::load_matrix_sync(af[i], Ah + (wr * 32 + i * 16) * LDM + k, LDM);
        #pragma unroll
        for (int j = 0; j < 2; j++)
            wmma::load_matrix_sync(bf[j], Bh + (wc * 32 + j * 16) * LDM + k, LDM);
        #pragma unroll
        for (int i = 0; i < 2; i++)
            #pragma unroll
            for (int j = 0; j < 2; j++)
                wmma::mma_sync(acc[i][j], af[i], bf[j], acc[i][j]);
    }
    __syncthreads();

    #pragma unroll
    for (int i = 0; i < 2; i++)
        #pragma unroll
        for (int j = 0; j < 2; j++)
            wmma::store_matrix_sync(Csf + (wr * 32 + i * 16) * CLD + wc * 32 + j * 16,
                                    acc[i][j], CLD, wmma::mem_row_major);
    __syncthreads();

    // fused alpha: CTA heads hb..hb+3; warp w -> rows w*8..+7
    {
        int hb = n0 >> 5;
        int hl = lane >> 3, k4 = lane & 7;
        float4 cs = ((const float4*)aS1)[(hb + hl) * 8 + k4];
        float4 cd = ((const float4*)aD1)[(hb + hl) * 8 + k4];
        #pragma unroll
        for (int rr = 0; rr < 8; rr++) {
            int r = wid * 8 + rr;
            float4 v = *(float4*)&Csf[r * CLD + hl * 32 + k4 * 4];
            float ps = v.x * cs.x + v.y * cs.y + v.z * cs.z + v.w * cs.w;
            float pd = v.x * cd.x + v.y * cd.y + v.z * cd.z + v.w * cd.w;
            #pragma unroll
            for (int off = 4; off; off >>= 1) {
                ps += __shfl_xor_sync(0xffffffffu, ps, off);
                pd += __shfl_xor_sync(0xffffffffu, pd, off);
            }
            int gr = m0 + r;
            if (k4 == 0 && gr < M) {
                as[gr * 8 + hb + hl] = ps;
                ad[gr * 8 + hb + hl] = pd;
            }
        }
    }
    // h1 store as fp16 (uint4 = 8 halves)
    for (int idx = tid; idx < 128 * 16; idx += 512) {
        int r = idx >> 4, c8 = idx & 15;
        if (m0 + r >= M) continue;
        float4 v0 = *(float4*)&Csf[r * CLD + c8 * 8];
        float4 v1 = *(float4*)&Csf[r * CLD + c8 * 8 + 4];
        __half2 p0 = __floats2half2_rn(v0.x, v0.y);
        __half2 p1 = __floats2half2_rn(v0.z, v0.w);
        __half2 p2 = __floats2half2_rn(v1.x, v1.y);
        __half2 p3 = __floats2half2_rn(v1.z, v1.w);
        uint4 pk;
        pk.x = *(unsigned*)&p0; pk.y = *(unsigned*)&p1;
        pk.z = *(unsigned*)&p2; pk.w = *(unsigned*)&p3;
        *(uint4*)(outh + (size_t)(m0 + r) * 256 + n0 + c8 * 8) = pk;
    }
}

// ---------------- merged conversions (x -> fp16; W1t -> fp16) --------------
__global__ void conv_k(const float4* __restrict__ x4, uint2* __restrict__ xh, int n4,
                       const float* __restrict__ W1, __half* __restrict__ wt) {
    int nxb = (n4 + 255) >> 8;
    if ((int)blockIdx.x < nxb) {
        int i = blockIdx.x * 256 + threadIdx.x;
        if (i >= n4) return;
        float4 v = x4[i];
        __half2 p0 = __floats2half2_rn(v.x, v.y);
        __half2 p1 = __floats2half2_rn(v.z, v.w);
        uint2 pk;
        pk.x = *(unsigned*)&p0; pk.y = *(unsigned*)&p1;
        xh[i] = pk;
    } else {
        int i = (blockIdx.x - nxb) * 256 + threadIdx.x;   // Wt[n,k] <- W[k,n]
        if (i >= 256 * 128) return;
        int n = i >> 7, k = i & 127;
        wt[i] = __float2half_rn(W1[k * 256 + n]);
    }
}

// ---------------- GEMM 128x64 SIMT + fused alpha + optional fp16 C ----------
__global__ void gemm_k(const float* __restrict__ A, const float* __restrict__ B,
                       const float* __restrict__ bias, void* __restrict__ Cv,
                       int M, int N, int K, int reluA, int halfC,
                       const float* __restrict__ aS, const float* __restrict__ aD,
                       float* __restrict__ als, float* __restrict__ ald, int H) {
    __shared__ float As[16][132];
    __shared__ float Bs[16][64];
    int tid = threadIdx.x;
    int ty = tid >> 4;
    int tx = tid & 15;
    int m0 = blockIdx.y * 128;
    int n0 = blockIdx.x * 64;
    float acc[8][4] = {};

    for (int k0 = 0; k0 < K; k0 += 16) {
        #pragma unroll
        for (int i = 0; i < 2; i++) {
            int L = tid + 256 * i;
            int row = L >> 2, q = (L & 3) << 2;
            float4 v = make_float4(0.f, 0.f, 0.f, 0.f);
            if (m0 + row < M) {
                v = *(const float4*)(A + (size_t)(m0 + row) * K + k0 + q);
                if (reluA) {
                    v.x = fmaxf(v.x, 0.f); v.y = fmaxf(v.y, 0.f);
                    v.z = fmaxf(v.z, 0.f); v.w = fmaxf(v.w, 0.f);
                }
            }
            As[q + 0][row] = v.x; As[q + 1][row] = v.y;
            As[q + 2][row] = v.z; As[q + 3][row] = v.w;
        }
        {
            int kl = tid >> 4, g = (tid & 15) << 2;
            float4 v = make_float4(0.f, 0.f, 0.f, 0.f);
            if (n0 + g < N)
                v = *(const float4*)(B + (size_t)(k0 + kl) * N + n0 + g);
            *(float4*)&Bs[kl][g] = v;
        }
        __syncthreads();
        #pragma unroll
        for (int kk = 0; kk < 16; kk++) {
            float a[8], b[4];
            *(float4*)&a[0] = *(const float4*)&As[kk][ty * 8];
            *(float4*)&a[4] = *(const float4*)&As[kk][ty * 8 + 4];
            *(float4*)&b[0] = *(const float4*)&Bs[kk][tx * 4];
            #pragma unroll
            for (int i = 0; i < 8; i++)
                #pragma unroll
                for (int j = 0; j < 4; j++)
                    acc[i][j] += a[i] * b[j];
        }
        __syncthreads();
    }
    int colb = n0 + tx * 4;
    if (colb < N) {
        float4 bv = make_float4(0.f, 0.f, 0.f, 0.f);
        if (bias) bv = *(const float4*)(bias + colb);
        #pragma unroll
        for (int i = 0; i < 8; i++) {
            int row = m0 + ty * 8 + i;
            if (row >= M) break;
            float4 v = make_float4(acc[i][0] + bv.x, acc[i][1] + bv.y,
                                   acc[i][2] + bv.z, acc[i][3] + bv.w);
            if (halfC) {
                __half2 p0 = __floats2half2_rn(v.x, v.y);
                __half2 p1 = __floats2half2_rn(v.z, v.w);
                uint2 pk;
                pk.x = *(unsigned*)&p0; pk.y = *(unsigned*)&p1;
                *(uint2*)((__half*)Cv + (size_t)row * N + colb) = pk;
            } else {
                *(float4*)((float*)Cv + (size_t)row * N + colb) = v;
            }
        }
    }
    if (als) {
        int hl = tx >> 3;
        int head = (n0 >> 5) + hl;
        float4 cs = make_float4(0.f, 0.f, 0.f, 0.f), cd = cs;
        if (head < H) {
            cs = ((const float4*)aS)[head * 8 + (tx & 7)];
            cd = ((const float4*)aD)[head * 8 + (tx & 7)];
        }
        #pragma unroll
        for (int i = 0; i < 8; i++) {
            float ps = acc[i][0] * cs.x + acc[i][1] * cs.y + acc[i][2] * cs.z + acc[i][3] * cs.w;
            float pd = acc[i][0] * cd.x + acc[i][1] * cd.y + acc[i][2] * cd.z + acc[i][3] * cd.w;
            #pragma unroll
            for (int off = 4; off; off >>= 1) {
                ps += __shfl_xor_sync(0xffffffffu, ps, off);
                pd += __shfl_xor_sync(0xffffffffu, pd, off);
            }
            int row = m0 + ty * 8 + i;
            if ((tx & 7) == 0 && head < H && row < M) {
                als[(size_t)row * H + head] = ps;
                ald[(size_t)row * H + head] = pd;
            }
        }
    }
}

// ---------------- CSR build ----------------
__global__ void init_cnt_k(int* cnt, int N) {
    int i = blockIdx.x * blockDim.x + threadIdx.x;
    if (i < N) cnt[i] = 1;
}
__global__ void hist_k(int* cnt, const int* __restrict__ dst, int E) {
    int e = blockIdx.x * blockDim.x + threadIdx.x;
    if (e < E) atomicAdd(&cnt[dst[e]], 1);
}
__global__ void scanA_k(const int* __restrict__ cnt, int* bsum, int N) {
    __shared__ int sm[256];
    int gi = blockIdx.x * 256 + threadIdx.x;
    int v = (gi < N) ? cnt[gi] : 0;
    sm[threadIdx.x] = v; __syncthreads();
    for (int off = 128; off; off >>= 1) {
        if (threadIdx.x < off) sm[threadIdx.x] += sm[threadIdx.x + off];
        __syncthreads();
    }
    if (threadIdx.x == 0) bsum[blockIdx.x] = sm[0];
}
__global__ void scanB_k(const int* __restrict__ bsum, int* boff, int nb) {
    __shared__ int sm[256];
    int t = threadIdx.x;
    int v = (t < nb) ? bsum[t] : 0;
    sm[t] = v; __syncthreads();
    #pragma unroll
    for (int off = 1; off < 256; off <<= 1) {
        int x = (t >= off) ? sm[t - off] : 0;
        __syncthreads();
        sm[t] += x;
        __syncthreads();
    }
    if (t < nb) boff[t] = sm[t] - v;
}
__global__ void scanC_k(const int* __restrict__ cnt, const int* __restrict__ boff,
                        int* row, int* cur, int N) {
    __shared__ int sm[256];
    int t = threadIdx.x;
    int gi = blockIdx.x * 256 + t;
    int v = (gi < N) ? cnt[gi] : 0;
    sm[t] = v; __syncthreads();
    #pragma unroll
    for (int off = 1; off < 256; off <<= 1) {
        int x = (t >= off) ? sm[t - off] : 0;
        __syncthreads();
        sm[t] += x;
        __syncthreads();
    }
    int excl = boff[blockIdx.x] + sm[t] - v;
    if (gi < N) { row[gi] = excl; cur[gi] = excl; }
    if (gi == N - 1) row[N] = excl + v;
}
__global__ void scatter_k(const int* __restrict__ src, const int* __restrict__ dst,
                          int* cur, int* esrc, int E, int ET) {
    int e = blockIdx.x * blockDim.x + threadIdx.x;
    if (e >= ET) return;
    int s_, d_;
    if (e < E) { s_ = src[e]; d_ = dst[e]; } else { s_ = d_ = e - E; }
    int pos = atomicAdd(&cur[d_], 1);
    esrc[pos] = s_;
}

// ---------------- fused GAT aggregate, layer 1 (H=8, C=32), fp16 gather ----
__global__ void gat8_k(const __half* __restrict__ h1,
                       const float* __restrict__ as, const float* __restrict__ ad,
                       const int* __restrict__ row, const int* __restrict__ esrc,
                       const float* __restrict__ bias, float* __restrict__ out, int N) {
    int w = (blockIdx.x * blockDim.x + threadIdx.x) >> 5;
    int l = threadIdx.x & 31;
    if (w >= N) return;
    int hgrp = l >> 2;
    int rs = row[w], re = row[w + 1];
    float adh = ad[w * 8 + hgrp];

    float mx = -3.0e38f;
    int s = esrc[rs];
    for (int i = rs; i < re; i++) {
        int sn = (i + 1 < re) ? esrc[i + 1] : 0;
        float v = lrelu(__ldg(as + s * 8 + hgrp) + adh);
        mx = fmaxf(mx, v);
        s = sn;
    }
    float sum = 0.f;
    float acc[8] = {};
    s = esrc[rs];
    for (int i = rs; i < re; i++) {
        int sn = (i + 1 < re) ? esrc[i + 1] : 0;
        float v = lrelu(__ldg(as + s * 8 + hgrp) + adh);
        float ex = expf(v - mx);
        sum += ex;
        uint4 raw = ((const uint4*)(h1 + (size_t)s * 256))[l];
        __half2* hh = (__half2*)&raw;
        float2 f0 = __half22float2(hh[0]);
        float2 f1 = __half22float2(hh[1]);
        float2 f2 = __half22float2(hh[2]);
        float2 f3 = __half22float2(hh[3]);
        acc[0] += ex * f0.x; acc[1] += ex * f0.y;
        acc[2] += ex * f1.x; acc[3] += ex * f1.y;
        acc[4] += ex * f2.x; acc[5] += ex * f2.y;
        acc[6] += ex * f3.x; acc[7] += ex * f3.y;
        s = sn;
    }
    float inv = 1.f / (sum + 1e-16f);
    float4 b0 = ((const float4*)bias)[2 * l];
    float4 b1 = ((const float4*)bias)[2 * l + 1];
    float4 o0 = make_float4(acc[0] * inv + b0.x, acc[1] * inv + b0.y,
                            acc[2] * inv + b0.z, acc[3] * inv + b0.w);
    float4 o1 = make_float4(acc[4] * inv + b1.x, acc[5] * inv + b1.y,
                            acc[6] * inv + b1.z, acc[7] * inv + b1.w);
    float4* op = (float4*)(out + (size_t)w * 256 + 8 * l);
    op[0] = o0; op[1] = o1;
}

// ---------------- fused GAT aggregate, layer 2 (H=1, C=32), fp16 gather ----
__global__ void gat1_k(const __half* __restrict__ h2,
                       const float* __restrict__ as, const float* __restrict__ ad,
                       const int* __restrict__ row, const int* __restrict__ esrc,
                       const float* __restrict__ bias, float* __restrict__ out, int N) {
    int w = (blockIdx.x * blockDim.x + threadIdx.x) >> 5;
    int l = threadIdx.x & 31;
    if (w >= N) return;
    int rs = row[w], re = row[w + 1];
    float adh = ad[w];

    float mx = -3.0e38f;
    int s = esrc[rs];
    for (int i = rs; i < re; i++) {
        int sn = (i + 1 < re) ? esrc[i + 1] : 0;
        float v = lrelu(__ldg(as + s) + adh);
        mx = fmaxf(mx, v);
        s = sn;
    }
    float sum = 0.f, acc = 0.f;
    s = esrc[rs];
    for (int i = rs; i < re; i++) {
        int sn = (i + 1 < re) ? esrc[i + 1] : 0;
        float v = lrelu(__ldg(as + s) + adh);
        float ex = expf(v - mx);
        sum += ex;
        acc += ex * __half2float(__ldg(h2 + (size_t)s * 32 + l));
        s = sn;
    }
    out[(size_t)w * 32 + l] = acc / (sum + 1e-16f) + bias[l];
}

// ---------------- launch ----------------
extern "C" void kernel_launch(void* const* d_in, const int* in_sizes, int n_in,
                              void* d_out, int out_size) {
    const float* x   = (const float*)d_in[0];
    const int*   ei  = (const int*)d_in[1];
    const float* W1  = (const float*)d_in[2];
    const float* aS1 = (const float*)d_in[3];
    const float* aD1 = (const float*)d_in[4];
    const float* b1  = (const float*)d_in[5];
    const float* W2  = (const float*)d_in[6];
    const float* aS2 = (const float*)d_in[7];
    const float* aD2 = (const float*)d_in[8];
    const float* b2  = (const float*)d_in[9];
    const float* Wd  = (const float*)d_in[10];
    const float* bd  = (const float*)d_in[11];
    float* out = (float*)d_out;

    int N  = in_sizes[0] / 128;
    int E  = in_sizes[1] / 2;
    int ET = E + N;
    const int* src = ei;
    const int* dst = ei + E;

    float *o1, *as1, *ad1, *z, *as2, *ad2;
    __half *h1h, *h2h, *xh, *wth;
    int *cnt, *row, *cur, *bsum, *boff, *esrc;
    cudaGetSymbolAddress((void**)&h1h,  g_h1h);
    cudaGetSymbolAddress((void**)&o1,   g_o1);
    cudaGetSymbolAddress((void**)&as1,  g_as1);
    cudaGetSymbolAddress((void**)&ad1,  g_ad1);
    cudaGetSymbolAddress((void**)&h2h,  g_h2h);
    cudaGetSymbolAddress((void**)&z,    g_z);
    cudaGetSymbolAddress((void**)&as2,  g_as2);
    cudaGetSymbolAddress((void**)&ad2,  g_ad2);
    cudaGetSymbolAddress((void**)&cnt,  g_cnt);
    cudaGetSymbolAddress((void**)&row,  g_row);
    cudaGetSymbolAddress((void**)&cur,  g_cur);
    cudaGetSymbolAddress((void**)&bsum, g_bsum);
    cudaGetSymbolAddress((void**)&boff, g_boff);
    cudaGetSymbolAddress((void**)&esrc, g_esrc);
    cudaGetSymbolAddress((void**)&xh,   g_xh);
    cudaGetSymbolAddress((void**)&wth,  g_wth);

    cudaFuncSetAttribute(gemm1_wmma_k, cudaFuncAttributeMaxDynamicSharedMemorySize, WSM_TOTAL);

    const int TB = 256;
    int mb = (N + 127) / 128;
    int nb = (N + 255) / 256;
    int n4 = N * 32;
    int nxb = (n4 + 255) / 256;

    init_cnt_k<<<nb, TB>>>(cnt, N);                                    // 1
    hist_k<<<(E + TB - 1) / TB, TB>>>(cnt, dst, E);                    // 2
    conv_k<<<nxb + 128, TB>>>((const float4*)x, (uint2*)xh, n4, W1, wth); // 3
    gemm1_wmma_k<<<dim3(2, mb), 512, WSM_TOTAL>>>(xh, wth, aS1, aD1,
                                                  h1h, as1, ad1, N);   // 4 (profiled)
    scanA_k<<<nb, TB>>>(cnt, bsum, N);                                 // 5
    scanB_k<<<1, TB>>>(bsum, boff, nb);                                // 6
    scanC_k<<<nb, TB>>>(cnt, boff, row, cur, N);                       // 7
    scatter_k<<<(ET + TB - 1) / TB, TB>>>(src, dst, cur, esrc, E, ET); // 8

    // ===== Layer 1 aggregate (fp16 gather) =====
    gat8_k<<<(N * 32 + TB - 1) / TB, TB>>>(h1h, as1, ad1, row, esrc, b1, o1, N); // 9

    // ===== Layer 2: GEMM2 (relu fused, alpha1 fused, fp16 C) =====
    gemm_k<<<dim3(1, mb), TB>>>(o1, W2, nullptr, h2h, N, 32, 256, 1, 1,
                                aS2, aD2, as2, ad2, 1);                // 10
    gat1_k<<<(N * 32 + TB - 1) / TB, TB>>>(h2h, as2, ad2, row, esrc, b2, z, N);  // 11

    // ===== Decoder (fp32) =====
    gemm_k<<<dim3(2, mb), TB>>>(z, Wd, bd, out, N, 128, 32, 0, 0,
                                nullptr, nullptr, nullptr, nullptr, 0); // 12
}

// round 16
// speedup vs baseline: 1.5829x; 1.2115x over previous
#include <cuda_runtime.h>
#include <cuda_fp16.h>
#include <mma.h>
#include <math.h>
#include <stdint.h>

using namespace nvcuda;

static const int MAXN = 50000;
static const int MAXE = 800000 + MAXN;

// ---------------- scratch ----------------
__device__ __half g_h1h[MAXN * 256];   // layer1 features, fp16
__device__ __half g_o1h[MAXN * 256];   // relu(layer1 out), fp16 (feeds GEMM2)
__device__ float  g_as1[MAXN * 8];
__device__ float  g_ad1[MAXN * 8];
__device__ __half g_h2h[MAXN * 32];    // layer2 features, fp16
__device__ float  g_z[MAXN * 32];
__device__ float  g_as2[MAXN];
__device__ float  g_ad2[MAXN];
__device__ int    g_cnt[MAXN];
__device__ int    g_row[MAXN + 1];
__device__ int    g_cur[MAXN];
__device__ int    g_bsum[256];
__device__ int    g_boff[256];
__device__ int    g_esrc[MAXE];
__device__ __half g_xh[MAXN * 128];    // x in fp16
__device__ __half g_wth[256 * 128];    // W1^T fp16
__device__ __half g_w2t[32 * 256];     // W2^T fp16

__device__ __forceinline__ float lrelu(float v) { return v > 0.f ? v : 0.2f * v; }

// ================= GEMM1 wmma fp16 + fused alpha8, fp16 out =================
static const int LDM = 136;
static const int CLD = 132;
static const int WSM_TOTAL = 2 * 128 * LDM * 2;   // 69632

__global__ __launch_bounds__(512, 2)
void gemm1_wmma_k(const __half* __restrict__ xh, const __half* __restrict__ wth,
                  const float* __restrict__ aS1, const float* __restrict__ aD1,
                  __half* __restrict__ outh, float* __restrict__ as, float* __restrict__ ad,
                  int M) {
    extern __shared__ char smraw[];
    __half* Ah = (__half*)smraw;
    __half* Bh = Ah + 128 * LDM;
    float* Csf = (float*)smraw;
    int tid = threadIdx.x, wid = tid >> 5, lane = tid & 31;
    int m0 = blockIdx.y * 128, n0 = blockIdx.x * 128;

    for (int idx = tid; idx < 128 * 16; idx += 512) {
        int r = idx >> 4, c = idx & 15;
        uint4 v = make_uint4(0u, 0u, 0u, 0u);
        if (m0 + r < M) v = ((const uint4*)xh)[(size_t)(m0 + r) * 16 + c];
        ((uint4*)(Ah + r * LDM))[c] = v;
    }
    for (int idx = tid; idx < 128 * 16; idx += 512) {
        int r = idx >> 4, c = idx & 15;
        ((uint4*)(Bh + r * LDM))[c] = ((const uint4*)wth)[(size_t)(n0 + r) * 16 + c];
    }
    __syncthreads();

    int wr = wid & 3, wc = wid >> 2;
    wmma::fragment<wmma::accumulator, 16, 16, 16, float> acc[2][2];
    #pragma unroll
    for (int i = 0; i < 2; i++)
        #pragma unroll
        for (int j = 0; j < 2; j++) wmma::fill_fragment(acc[i][j], 0.f);

    #pragma unroll
    for (int k = 0; k < 128; k += 16) {
        wmma::fragment<wmma::matrix_a, 16, 16, 16, __half, wmma::row_major> af[2];
        wmma::fragment<wmma::matrix_b, 16, 16, 16, __half, wmma::col_major> bf[2];
        #pragma unroll
        for (int i = 0; i < 2; i++)
            wmma::load_matrix_sync(af[i], Ah + (wr * 32 + i * 16) * LDM + k, LDM);
        #pragma unroll
        for (int j = 0; j < 2; j++)
            wmma::load_matrix_sync(bf[j], Bh + (wc * 32 + j * 16) * LDM + k, LDM);
        #pragma unroll
        for (int i = 0; i < 2; i++)
            #pragma unroll
            for (int j = 0; j < 2; j++)
                wmma::mma_sync(acc[i][j], af[i], bf[j], acc[i][j]);
    }
    __syncthreads();

    #pragma unroll
    for (int i = 0; i < 2; i++)
        #pragma unroll
        for (int j = 0; j < 2; j++)
            wmma::store_matrix_sync(Csf + (wr * 32 + i * 16) * CLD + wc * 32 + j * 16,
                                    acc[i][j], CLD, wmma::mem_row_major);
    __syncthreads();

    // fused alpha8
    {
        int hb = n0 >> 5;
        int hl = lane >> 3, k4 = lane & 7;
        float4 cs = ((const float4*)aS1)[(hb + hl) * 8 + k4];
        float4 cd = ((const float4*)aD1)[(hb + hl) * 8 + k4];
        #pragma unroll
        for (int rr = 0; rr < 8; rr++) {
            int r = wid * 8 + rr;
            float4 v = *(float4*)&Csf[r * CLD + hl * 32 + k4 * 4];
            float ps = v.x * cs.x + v.y * cs.y + v.z * cs.z + v.w * cs.w;
            float pd = v.x * cd.x + v.y * cd.y + v.z * cd.z + v.w * cd.w;
            #pragma unroll
            for (int off = 4; off; off >>= 1) {
                ps += __shfl_xor_sync(0xffffffffu, ps, off);
                pd += __shfl_xor_sync(0xffffffffu, pd, off);
            }
            int gr = m0 + r;
            if (k4 == 0 && gr < M) {
                as[gr * 8 + hb + hl] = ps;
                ad[gr * 8 + hb + hl] = pd;
            }
        }
    }
    // h1 store as fp16
    for (int idx = tid; idx < 128 * 16; idx += 512) {
        int r = idx >> 4, c8 = idx & 15;
        if (m0 + r >= M) continue;
        float4 v0 = *(float4*)&Csf[r * CLD + c8 * 8];
        float4 v1 = *(float4*)&Csf[r * CLD + c8 * 8 + 4];
        __half2 p0 = __floats2half2_rn(v0.x, v0.y);
        __half2 p1 = __floats2half2_rn(v0.z, v0.w);
        __half2 p2 = __floats2half2_rn(v1.x, v1.y);
        __half2 p3 = __floats2half2_rn(v1.z, v1.w);
        uint4 pk;
        pk.x = *(unsigned*)&p0; pk.y = *(unsigned*)&p1;
        pk.z = *(unsigned*)&p2; pk.w = *(unsigned*)&p3;
        *(uint4*)(outh + (size_t)(m0 + r) * 256 + n0 + c8 * 8) = pk;
    }
}

// ================= GEMM2 wmma fp16 + fused alpha1, fp16 out =================
// h2[M,32] = relu_o1[M,256] @ W2[256,32]; A already relu'd fp16. K chunks of 64.
static const int G2LD = 72;   // smem leading dim (halves)

__global__ __launch_bounds__(256)
void gemm2_wmma_k(const __half* __restrict__ Ahg, const __half* __restrict__ w2t,
                  const float* __restrict__ aS2, const float* __restrict__ aD2,
                  __half* __restrict__ h2h, float* __restrict__ as2, float* __restrict__ ad2,
                  int M) {
    __shared__ __half As[128 * G2LD];
    __shared__ __half Bs[32 * G2LD];
    float* Csf = (float*)As;                       // 128*36*4 = 18432 <= 18432
    int tid = threadIdx.x, wid = tid >> 5;
    int m0 = blockIdx.x * 128;
    int wr = wid & 3, wc = wid >> 2;               // rows wr*32..+31, cols wc*16..+15

    wmma::fragment<wmma::accumulator, 16, 16, 16, float> acc[2];
    wmma::fill_fragment(acc[0], 0.f);
    wmma::fill_fragment(acc[1], 0.f);

    for (int kc = 0; kc < 256; kc += 64) {
        #pragma unroll
        for (int idx = tid; idx < 128 * 8; idx += 256) {
            int r = idx >> 3, c = idx & 7;
            uint4 v = make_uint4(0u, 0u, 0u, 0u);
            if (m0 + r < M) v = ((const uint4*)Ahg)[(size_t)(m0 + r) * 32 + (kc >> 3) + c];
            ((uint4*)(As + r * G2LD))[c] = v;
        }
        {
            int r = tid >> 3, c = tid & 7;         // 256 = 32*8 exactly
            ((uint4*)(Bs + r * G2LD))[c] = ((const uint4*)w2t)[(size_t)r * 32 + (kc >> 3) + c];
        }
        __syncthreads();
        #pragma unroll
        for (int k = 0; k < 64; k += 16) {
            wmma::fragment<wmma::matrix_a, 16, 16, 16, __half, wmma::row_major> af[2];
            wmma::fragment<wmma::matrix_b, 16, 16, 16, __half, wmma::col_major> bf;
            wmma::load_matrix_sync(af[0], As + (wr * 32) * G2LD + k, G2LD);
            wmma::load_matrix_sync(af[1], As + (wr * 32 + 16) * G2LD + k, G2LD);
            wmma::load_matrix_sync(bf, Bs + (wc * 16) * G2LD + k, G2LD);
            wmma::mma_sync(acc[0], af[0], bf, acc[0]);
            wmma::mma_sync(acc[1], af[1], bf, acc[1]);
        }
        __syncthreads();
    }
    wmma::store_matrix_sync(Csf + (wr * 32) * 36 + wc * 16, acc[0], 36, wmma::mem_row_major);
    wmma::store_matrix_sync(Csf + (wr * 32 + 16) * 36 + wc * 16, acc[1], 36, wmma::mem_row_major);
    __syncthreads();

    // fused alpha1 + fp16 h2 store: 2 threads per row (16 cols each)
    int r = tid >> 1, hf = tid & 1;
    float ps = 0.f, pd = 0.f;
    #pragma unroll
    for (int j = 0; j < 4; j++) {
        float4 v = *(float4*)&Csf[r * 36 + hf * 16 + j * 4];
        float4 cs = ((const float4*)aS2)[hf * 4 + j];
        float4 cd = ((const float4*)aD2)[hf * 4 + j];
        ps += v.x * cs.x + v.y * cs.y + v.z * cs.z + v.w * cs.w;
        pd += v.x * cd.x + v.y * cd.y + v.z * cd.z + v.w * cd.w;
    }
    ps += __shfl_xor_sync(0xffffffffu, ps, 1);
    pd += __shfl_xor_sync(0xffffffffu, pd, 1);
    if (m0 + r < M) {
        if (hf == 0) { as2[m0 + r] = ps; ad2[m0 + r] = pd; }
        #pragma unroll
        for (int u = 0; u < 2; u++) {
            float4 v0 = *(float4*)&Csf[r * 36 + hf * 16 + u * 8];
            float4 v1 = *(float4*)&Csf[r * 36 + hf * 16 + u * 8 + 4];
            __half2 p0 = __floats2half2_rn(v0.x, v0.y);
            __half2 p1 = __floats2half2_rn(v0.z, v0.w);
            __half2 p2 = __floats2half2_rn(v1.x, v1.y);
            __half2 p3 = __floats2half2_rn(v1.z, v1.w);
            uint4 pk;
            pk.x = *(unsigned*)&p0; pk.y = *(unsigned*)&p1;
            pk.z = *(unsigned*)&p2; pk.w = *(unsigned*)&p3;
            *(uint4*)(h2h + (size_t)(m0 + r) * 32 + hf * 16 + u * 8) = pk;
        }
    }
}

// ---------------- merged conversions (x, W1t, W2t -> fp16) -----------------
__global__ void conv_k(const float4* __restrict__ x4, uint2* __restrict__ xh, int n4,
                       const float* __restrict__ W1, __half* __restrict__ wt,
                       const float* __restrict__ W2, __half* __restrict__ w2t) {
    int nxb = (n4 + 255) >> 8;
    int bid = blockIdx.x;
    if (bid < nxb) {
        int i = bid * 256 + threadIdx.x;
        if (i >= n4) return;
        float4 v = x4[i];
        __half2 p0 = __floats2half2_rn(v.x, v.y);
        __half2 p1 = __floats2half2_rn(v.z, v.w);
        uint2 pk;
        pk.x = *(unsigned*)&p0; pk.y = *(unsigned*)&p1;
        xh[i] = pk;
    } else if (bid < nxb + 128) {
        int i = (bid - nxb) * 256 + threadIdx.x;   // W1t[n,k] <- W1[k,n]; 256x128
        if (i >= 256 * 128) return;
        int n = i >> 7, k = i & 127;
        wt[i] = __float2half_rn(W1[k * 256 + n]);
    } else {
        int i = (bid - nxb - 128) * 256 + threadIdx.x;  // W2t[n,k] <- W2[k,n]; 32x256
        if (i >= 32 * 256) return;
        int n = i >> 8, k = i & 255;
        w2t[i] = __float2half_rn(W2[k * 32 + n]);
    }
}

// ---------------- GEMM 128x64 SIMT (decoder only, fp32) ----------------
__global__ void gemm_k(const float* __restrict__ A, const float* __restrict__ B,
                       const float* __restrict__ bias, float* __restrict__ C,
                       int M, int N, int K) {
    __shared__ float As[16][132];
    __shared__ float Bs[16][64];
    int tid = threadIdx.x;
    int ty = tid >> 4;
    int tx = tid & 15;
    int m0 = blockIdx.y * 128;
    int n0 = blockIdx.x * 64;
    float acc[8][4] = {};

    for (int k0 = 0; k0 < K; k0 += 16) {
        #pragma unroll
        for (int i = 0; i < 2; i++) {
            int L = tid + 256 * i;
            int row = L >> 2, q = (L & 3) << 2;
            float4 v = make_float4(0.f, 0.f, 0.f, 0.f);
            if (m0 + row < M)
                v = *(const float4*)(A + (size_t)(m0 + row) * K + k0 + q);
            As[q + 0][row] = v.x; As[q + 1][row] = v.y;
            As[q + 2][row] = v.z; As[q + 3][row] = v.w;
        }
        {
            int kl = tid >> 4, g = (tid & 15) << 2;
            float4 v = make_float4(0.f, 0.f, 0.f, 0.f);
            if (n0 + g < N)
                v = *(const float4*)(B + (size_t)(k0 + kl) * N + n0 + g);
            *(float4*)&Bs[kl][g] = v;
        }
        __syncthreads();
        #pragma unroll
        for (int kk = 0; kk < 16; kk++) {
            float a[8], b[4];
            *(float4*)&a[0] = *(const float4*)&As[kk][ty * 8];
            *(float4*)&a[4] = *(const float4*)&As[kk][ty * 8 + 4];
            *(float4*)&b[0] = *(const float4*)&Bs[kk][tx * 4];
            #pragma unroll
            for (int i = 0; i < 8; i++)
                #pragma unroll
                for (int j = 0; j < 4; j++)
                    acc[i][j] += a[i] * b[j];
        }
        __syncthreads();
    }
    int colb = n0 + tx * 4;
    if (colb < N) {
        float4 bv = make_float4(0.f, 0.f, 0.f, 0.f);
        if (bias) bv = *(const float4*)(bias + colb);
        #pragma unroll
        for (int i = 0; i < 8; i++) {
            int row = m0 + ty * 8 + i;
            if (row >= M) break;
            float4 v = make_float4(acc[i][0] + bv.x, acc[i][1] + bv.y,
                                   acc[i][2] + bv.z, acc[i][3] + bv.w);
            *(float4*)(C + (size_t)row * N + colb) = v;
        }
    }
}

// ---------------- CSR build ----------------
__global__ void init_cnt_k(int* cnt, int N) {
    int i = blockIdx.x * blockDim.x + threadIdx.x;
    if (i < N) cnt[i] = 1;
}
__global__ void hist_k(int* cnt, const int* __restrict__ dst, int E) {
    int e = blockIdx.x * blockDim.x + threadIdx.x;
    if (e < E) atomicAdd(&cnt[dst[e]], 1);
}
__global__ void scanA_k(const int* __restrict__ cnt, int* bsum, int N) {
    __shared__ int sm[256];
    int gi = blockIdx.x * 256 + threadIdx.x;
    int v = (gi < N) ? cnt[gi] : 0;
    sm[threadIdx.x] = v; __syncthreads();
    for (int off = 128; off; off >>= 1) {
        if (threadIdx.x < off) sm[threadIdx.x] += sm[threadIdx.x + off];
        __syncthreads();
    }
    if (threadIdx.x == 0) bsum[blockIdx.x] = sm[0];
}
__global__ void scanB_k(const int* __restrict__ bsum, int* boff, int nb) {
    __shared__ int sm[256];
    int t = threadIdx.x;
    int v = (t < nb) ? bsum[t] : 0;
    sm[t] = v; __syncthreads();
    #pragma unroll
    for (int off = 1; off < 256; off <<= 1) {
        int x = (t >= off) ? sm[t - off] : 0;
        __syncthreads();
        sm[t] += x;
        __syncthreads();
    }
    if (t < nb) boff[t] = sm[t] - v;
}
__global__ void scanC_k(const int* __restrict__ cnt, const int* __restrict__ boff,
                        int* row, int* cur, int N) {
    __shared__ int sm[256];
    int t = threadIdx.x;
    int gi = blockIdx.x * 256 + t;
    int v = (gi < N) ? cnt[gi] : 0;
    sm[t] = v; __syncthreads();
    #pragma unroll
    for (int off = 1; off < 256; off <<= 1) {
        int x = (t >= off) ? sm[t - off] : 0;
        __syncthreads();
        sm[t] += x;
        __syncthreads();
    }
    int excl = boff[blockIdx.x] + sm[t] - v;
    if (gi < N) { row[gi] = excl; cur[gi] = excl; }
    if (gi == N - 1) row[N] = excl + v;
}
__global__ void scatter_k(const int* __restrict__ src, const int* __restrict__ dst,
                          int* cur, int* esrc, int E, int ET) {
    int e = blockIdx.x * blockDim.x + threadIdx.x;
    if (e >= ET) return;
    int s_, d_;
    if (e < E) { s_ = src[e]; d_ = dst[e]; } else { s_ = d_ = e - E; }
    int pos = atomicAdd(&cur[d_], 1);
    esrc[pos] = s_;
}

// ---------------- fused GAT aggregate, layer 1: fp16 gather, fp16+relu out --
__global__ void gat8_k(const __half* __restrict__ h1,
                       const float* __restrict__ as, const float* __restrict__ ad,
                       const int* __restrict__ row, const int* __restrict__ esrc,
                       const float* __restrict__ bias, __half* __restrict__ outh, int N) {
    int w = (blockIdx.x * blockDim.x + threadIdx.x) >> 5;
    int l = threadIdx.x & 31;
    if (w >= N) return;
    int hgrp = l >> 2;
    int rs = row[w], re = row[w + 1];
    float adh = ad[w * 8 + hgrp];

    float mx = -3.0e38f;
    int s = esrc[rs];
    for (int i = rs; i < re; i++) {
        int sn = (i + 1 < re) ? esrc[i + 1] : 0;
        float v = lrelu(__ldg(as + s * 8 + hgrp) + adh);
        mx = fmaxf(mx, v);
        s = sn;
    }
    float sum = 0.f;
    float acc[8] = {};
    s = esrc[rs];
    for (int i = rs; i < re; i++) {
        int sn = (i + 1 < re) ? esrc[i + 1] : 0;
        float v = lrelu(__ldg(as + s * 8 + hgrp) + adh);
        float ex = expf(v - mx);
        sum += ex;
        uint4 raw = ((const uint4*)(h1 + (size_t)s * 256))[l];
        __half2* hh = (__half2*)&raw;
        float2 f0 = __half22float2(hh[0]);
        float2 f1 = __half22float2(hh[1]);
        float2 f2 = __half22float2(hh[2]);
        float2 f3 = __half22float2(hh[3]);
        acc[0] += ex * f0.x; acc[1] += ex * f0.y;
        acc[2] += ex * f1.x; acc[3] += ex * f1.y;
        acc[4] += ex * f2.x; acc[5] += ex * f2.y;
        acc[6] += ex * f3.x; acc[7] += ex * f3.y;
        s = sn;
    }
    float inv = 1.f / (sum + 1e-16f);
    float4 b0 = ((const float4*)bias)[2 * l];
    float4 b1 = ((const float4*)bias)[2 * l + 1];
    // relu + fp16 pack (o1 feeds GEMM2 only, which needs relu(o1))
    float o[8];
    o[0] = fmaxf(acc[0] * inv + b0.x, 0.f); o[1] = fmaxf(acc[1] * inv + b0.y, 0.f);
    o[2] = fmaxf(acc[2] * inv + b0.z, 0.f); o[3] = fmaxf(acc[3] * inv + b0.w, 0.f);
    o[4] = fmaxf(acc[4] * inv + b1.x, 0.f); o[5] = fmaxf(acc[5] * inv + b1.y, 0.f);
    o[6] = fmaxf(acc[6] * inv + b1.z, 0.f); o[7] = fmaxf(acc[7] * inv + b1.w, 0.f);
    __half2 p0 = __floats2half2_rn(o[0], o[1]);
    __half2 p1 = __floats2half2_rn(o[2], o[3]);
    __half2 p2 = __floats2half2_rn(o[4], o[5]);
    __half2 p3 = __floats2half2_rn(o[6], o[7]);
    uint4 pk;
    pk.x = *(unsigned*)&p0; pk.y = *(unsigned*)&p1;
    pk.z = *(unsigned*)&p2; pk.w = *(unsigned*)&p3;
    *(uint4*)(outh + (size_t)w * 256 + 8 * l) = pk;
}

// ---------------- fused GAT aggregate, layer 2 (H=1, C=32), fp16 gather ----
__global__ void gat1_k(const __half* __restrict__ h2,
                       const float* __restrict__ as, const float* __restrict__ ad,
                       const int* __restrict__ row, const int* __restrict__ esrc,
                       const float* __restrict__ bias, float* __restrict__ out, int N) {
    int w = (blockIdx.x * blockDim.x + threadIdx.x) >> 5;
    int l = threadIdx.x & 31;
    if (w >= N) return;
    int rs = row[w], re = row[w + 1];
    float adh = ad[w];

    float mx = -3.0e38f;
    int s = esrc[rs];
    for (int i = rs; i < re; i++) {
        int sn = (i + 1 < re) ? esrc[i + 1] : 0;
        float v = lrelu(__ldg(as + s) + adh);
        mx = fmaxf(mx, v);
        s = sn;
    }
    float sum = 0.f, acc = 0.f;
    s = esrc[rs];
    for (int i = rs; i < re; i++) {
        int sn = (i + 1 < re) ? esrc[i + 1] : 0;
        float v = lrelu(__ldg(as + s) + adh);
        float ex = expf(v - mx);
        sum += ex;
        acc += ex * __half2float(__ldg(h2 + (size_t)s * 32 + l));
        s = sn;
    }
    out[(size_t)w * 32 + l] = acc / (sum + 1e-16f) + bias[l];
}

// ---------------- launch ----------------
extern "C" void kernel_launch(void* const* d_in, const int* in_sizes, int n_in,
                              void* d_out, int out_size) {
    const float* x   = (const float*)d_in[0];
    const int*   ei  = (const int*)d_in[1];
    const float* W1  = (const float*)d_in[2];
    const float* aS1 = (const float*)d_in[3];
    const float* aD1 = (const float*)d_in[4];
    const float* b1  = (const float*)d_in[5];
    const float* W2  = (const float*)d_in[6];
    const float* aS2 = (const float*)d_in[7];
    const float* aD2 = (const float*)d_in[8];
    const float* b2  = (const float*)d_in[9];
    const float* Wd  = (const float*)d_in[10];
    const float* bd  = (const float*)d_in[11];
    float* out = (float*)d_out;

    int N  = in_sizes[0] / 128;
    int E  = in_sizes[1] / 2;
    int ET = E + N;
    const int* src = ei;
    const int* dst = ei + E;

    float *as1, *ad1, *z, *as2, *ad2;
    __half *h1h, *o1h, *h2h, *xh, *wth, *w2t;
    int *cnt, *row, *cur, *bsum, *boff, *esrc;
    cudaGetSymbolAddress((void**)&h1h,  g_h1h);
    cudaGetSymbolAddress((void**)&o1h,  g_o1h);
    cudaGetSymbolAddress((void**)&as1,  g_as1);
    cudaGetSymbolAddress((void**)&ad1,  g_ad1);
    cudaGetSymbolAddress((void**)&h2h,  g_h2h);
    cudaGetSymbolAddress((void**)&z,    g_z);
    cudaGetSymbolAddress((void**)&as2,  g_as2);
    cudaGetSymbolAddress((void**)&ad2,  g_ad2);
    cudaGetSymbolAddress((void**)&cnt,  g_cnt);
    cudaGetSymbolAddress((void**)&row,  g_row);
    cudaGetSymbolAddress((void**)&cur,  g_cur);
    cudaGetSymbolAddress((void**)&bsum, g_bsum);
    cudaGetSymbolAddress((void**)&boff, g_boff);
    cudaGetSymbolAddress((void**)&esrc, g_esrc);
    cudaGetSymbolAddress((void**)&xh,   g_xh);
    cudaGetSymbolAddress((void**)&wth,  g_wth);
    cudaGetSymbolAddress((void**)&w2t,  g_w2t);

    cudaFuncSetAttribute(gemm1_wmma_k, cudaFuncAttributeMaxDynamicSharedMemorySize, WSM_TOTAL);

    const int TB = 256;
    int mb = (N + 127) / 128;
    int nb = (N + 255) / 256;
    int n4 = N * 32;
    int nxb = (n4 + 255) / 256;

    init_cnt_k<<<nb, TB>>>(cnt, N);                                    // 1
    hist_k<<<(E + TB - 1) / TB, TB>>>(cnt, dst, E);                    // 2
    conv_k<<<nxb + 128 + 32, TB>>>((const float4*)x, (uint2*)xh, n4,
                                   W1, wth, W2, w2t);                  // 3
    gemm1_wmma_k<<<dim3(2, mb), 512, WSM_TOTAL>>>(xh, wth, aS1, aD1,
                                                  h1h, as1, ad1, N);   // 4 (profiled)
    scanA_k<<<nb, TB>>>(cnt, bsum, N);                                 // 5
    scanB_k<<<1, TB>>>(bsum, boff, nb);                                // 6
    scanC_k<<<nb, TB>>>(cnt, boff, row, cur, N);                       // 7
    scatter_k<<<(ET + TB - 1) / TB, TB>>>(src, dst, cur, esrc, E, ET); // 8

    // ===== Layer 1 aggregate (fp16 gather, fp16+relu out) =====
    gat8_k<<<(N * 32 + TB - 1) / TB, TB>>>(h1h, as1, ad1, row, esrc, b1, o1h, N); // 9

    // ===== Layer 2: wmma GEMM2 (alpha1 fused, fp16 out) =====
    gemm2_wmma_k<<<mb, TB>>>(o1h, w2t, aS2, aD2, h2h, as2, ad2, N);    // 10
    gat1_k<<<(N * 32 + TB - 1) / TB, TB>>>(h2h, as2, ad2, row, esrc, b2, z, N);   // 11

    // ===== Decoder (fp32 SIMT) =====
    gemm_k<<<dim3(2, mb), TB>>>(z, Wd, bd, out, N, 128, 32);           // 12
}